// round 1
// baseline (speedup 1.0000x reference)
#include <cuda_runtime.h>

namespace {
constexpr int B = 2, H = 128, W = 256, MD = 34, LD = 32;
constexpr int NH = 4, SH = 64, K = 25, P = 7, R = 3;
constexpr int FF1 = 512, FF2 = 256;
constexpr int PP = P * P; // 49

// ---------------- Kernel A (disco + head MLP + residual) config ----------------
constexpr int TW   = 32;          // longitude pixels per block
constexpr int PIX  = 8;           // pixels per inner group
constexpr int NGRP = TW / PIX;    // 4
constexpr int TA   = 512;         // threads
constexpr int XCOLS = TW + 2 * R; // 38

// smem offsets (in floats)
constexpr int OFF_WEFF = 0;                      // 64*49   = 3136
constexpr int OFF_SX   = OFF_WEFF + SH * PP;     // 32*7*38 = 8512
constexpr int OFF_SD   = OFF_SX + LD * P * XCOLS;// 256*65  = 16640 (pad 65 vs 64)
constexpr int OFF_HW1  = OFF_SD + PIX * LD * 65; // 64*32*4 = 8192  layout [s][o][n]
constexpr int OFF_RED  = OFF_HW1 + SH * 32 * NH; // 16*8*32 = 4096
constexpr int OFF_HB1  = OFF_RED + 16 * PIX * 32;// 128
constexpr int OFF_HW2  = OFF_HB1 + NH * 32;      // 128
constexpr int OFF_HB2  = OFF_HW2 + NH * 32;      // 4
constexpr int OFF_DB   = OFF_HB2 + NH;           // 64
constexpr int SMEM_A_F = OFF_DB + SH;            // total floats (= 40900)

// ---------------- Kernel B (FFN) config ----------------
constexpr int ROWS = 64;
constexpr int TB   = 256;
constexpr int OFF_IN = 0;                    // 64*34  = 2176
constexpr int OFF_T1 = OFF_IN + ROWS * MD;   // 64*512 = 32768
constexpr int OFF_T2 = OFF_T1 + ROWS * FF1;  // 64*256 = 16384
constexpr int SMEM_B_F = OFF_T2 + ROWS * FF2;// total floats (= 51328)

__device__ __forceinline__ float gelu_exact(float v) {
    return 0.5f * v * (1.0f + erff(v * 0.70710678118654752440f));
}
} // namespace

// =====================================================================
// Kernel A: DISCO sparse-basis conv + per-head MLP + residual.
// Writes x_mid into out[..., :32] and copies sin_cos into out[..., 32:34].
// =====================================================================
__global__ __launch_bounds__(TA) void disco_head_kernel(
    const float* __restrict__ x,   const float* __restrict__ psi,
    const float* __restrict__ dw,  const float* __restrict__ db,
    const float* __restrict__ hw1, const float* __restrict__ hb1,
    const float* __restrict__ hw2, const float* __restrict__ hb2,
    float* __restrict__ out)
{
    extern __shared__ float sm[];
    float* weff = sm + OFF_WEFF;
    float* sx   = sm + OFF_SX;
    float* sd   = sm + OFF_SD;
    float* shw1 = sm + OFF_HW1;
    float* sred = sm + OFF_RED;
    float* shb1 = sm + OFF_HB1;
    float* shw2 = sm + OFF_HW2;
    float* shb2 = sm + OFF_HB2;
    float* sdb  = sm + OFF_DB;

    const int tid = threadIdx.x;
    const int w0  = blockIdx.x * TW;
    const int h   = blockIdx.y;
    const int b   = blockIdx.z;

    // ---- load small weights; hw1 transposed to [s][o][n] so head index is
    //      the fast (conflict-free) axis for the phase-2 access pattern
    for (int i = tid; i < NH * SH * 32; i += TA) {
        int o = i & 31; int s = (i >> 5) & 63; int n = i >> 11;
        shw1[(s * 32 + o) * NH + n] = hw1[i];
    }
    for (int i = tid; i < NH * 32; i += TA) { shb1[i] = hb1[i]; shw2[i] = hw2[i]; }
    if (tid < NH) shb2[tid] = hb2[tid];
    if (tid < SH) sdb[tid]  = db[tid];

    // ---- fold psi_val into disco_w for this latitude: w_eff[f][p]
    for (int i = tid; i < SH * PP; i += TA) {
        int f = i / PP, p = i % PP;
        float acc = 0.f;
        #pragma unroll
        for (int k = 0; k < K; k++)
            acc += dw[f * K + k] * psi[(k * H + h) * PP + p];
        weff[i] = acc;
    }

    // ---- stencil tile: 32 channels x 7 lat rows (edge-clamped) x 38 lon cols (wrapped)
    for (int i = tid; i < LD * P * XCOLS; i += TA) {
        int ld = i & 31; int pos = i >> 5;
        int r = pos / XCOLS, c = pos % XCOLS;
        int lat = h + r - R; lat = lat < 0 ? 0 : (lat > H - 1 ? H - 1 : lat);
        int lon = (w0 + c - R + W) & (W - 1);
        sx[(ld * P + r) * XCOLS + c] = x[((b * H + lat) * W + lon) * MD + ld];
    }

    // ---- sin_cos passthrough channels 32..33
    for (int i = tid; i < TW * 2; i += TA) {
        int px = i >> 1, j = i & 1;
        int gi = ((b * H + h) * W + (w0 + px)) * MD + LD + j;
        out[gi] = x[gi];
    }
    __syncthreads();

    for (int g = 0; g < NGRP; g++) {
        const int pxb = g * PIX;

        // ======= phase 1: d[pix][ld][s] = bias + sum_p weff[s][p]*x_tap[p] =======
        // thread: (s-half, pix, ld). x taps live in registers; weff loads are
        // warp-uniform broadcasts (all lanes same (s,p)) -> FMA-pipe bound.
        {
            const int sg  = tid >> 8;      // 0..1 : which 32 s values
            const int pr  = tid & 255;     // pix*32 + ld
            const int pix = pr >> 5, ld = pr & 31;
            float xr[PP];
            #pragma unroll
            for (int r = 0; r < P; r++)
                #pragma unroll
                for (int cc = 0; cc < P; cc++)
                    xr[r * P + cc] = sx[(ld * P + r) * XCOLS + (pxb + pix + cc)];
            #pragma unroll 4
            for (int si = 0; si < 32; si++) {
                const int s = sg * 32 + si;
                float acc = sdb[s];
                const float* wf = weff + s * PP;
                #pragma unroll
                for (int p = 0; p < PP; p++) acc = fmaf(wf[p], xr[p], acc);
                sd[pr * 65 + s] = acc;
            }
        }
        __syncthreads();

        // ======= phase 2: head MLP. warp owns an o-pair, lane = ld. =======
        {
            const int wp = tid >> 5, lane = tid & 31;
            const int o0 = 2 * wp, o1 = 2 * wp + 1;
            const int n  = lane >> 3;
            float a0[PIX], a1[PIX];
            const float b0 = shb1[n * 32 + o0], b1 = shb1[n * 32 + o1];
            #pragma unroll
            for (int px = 0; px < PIX; px++) { a0[px] = b0; a1[px] = b1; }
            for (int s = 0; s < SH; s++) {
                const float w0v = shw1[(s * 32 + o0) * NH + n];
                const float w1v = shw1[(s * 32 + o1) * NH + n];
                #pragma unroll
                for (int px = 0; px < PIX; px++) {
                    const float dv = sd[(px * 32 + lane) * 65 + s];
                    a0[px] = fmaf(dv, w0v, a0[px]);
                    a1[px] = fmaf(dv, w1v, a1[px]);
                }
            }
            const float h2a = shw2[n * 32 + o0], h2b = shw2[n * 32 + o1];
            #pragma unroll
            for (int px = 0; px < PIX; px++) {
                float v = gelu_exact(a0[px]) * h2a + gelu_exact(a1[px]) * h2b;
                sred[(wp * PIX + px) * 32 + lane] = v;
            }
        }
        __syncthreads();

        // ======= cross-warp o reduction + hb2 + residual + store =======
        if (tid < PIX * 32) {
            const int px = tid >> 5, ld = tid & 31;
            float acc = 0.f;
            #pragma unroll
            for (int wp = 0; wp < 16; wp++) acc += sred[(wp * PIX + px) * 32 + ld];
            const int n = ld >> 3;
            acc += shb2[n] + sx[(ld * P + R) * XCOLS + (pxb + px + R)];
            out[((b * H + h) * W + (w0 + pxb + px)) * MD + ld] = acc;
        }
        __syncthreads();
    }
}

// =====================================================================
// Kernel B: fused FFN 34 -> 512 -> 256 -> 32 (+residual), in-place on out.
// =====================================================================
__global__ __launch_bounds__(TB) void ffn_kernel(
    const float* __restrict__ fw1, const float* __restrict__ fb1,
    const float* __restrict__ fw2, const float* __restrict__ fb2,
    const float* __restrict__ fw3, const float* __restrict__ fb3,
    float* __restrict__ out)
{
    extern __shared__ float sm[];
    float* sin_ = sm + OFF_IN;
    float* st1  = sm + OFF_T1;
    float* st2  = sm + OFF_T2;
    const int tid = threadIdx.x;
    const long r0 = (long)blockIdx.x * ROWS;

    for (int i = tid; i < ROWS * MD; i += TB)
        sin_[i] = out[r0 * MD + i];
    __syncthreads();

    // ---- stage 1: T1 = gelu(X @ fw1 + fb1), K = 34 (fw1 is L1-resident)
    {
        const int c0 = tid, c1 = tid + 256;
        const float bb0 = fb1[c0], bb1 = fb1[c1];
        for (int rc = 0; rc < ROWS / 8; rc++) {
            float a0[8], a1[8];
            #pragma unroll
            for (int rr = 0; rr < 8; rr++) { a0[rr] = bb0; a1[rr] = bb1; }
            #pragma unroll 2
            for (int i = 0; i < MD; i++) {
                const float w0v = fw1[i * FF1 + c0];
                const float w1v = fw1[i * FF1 + c1];
                #pragma unroll
                for (int rr = 0; rr < 8; rr++) {
                    const float xv = sin_[(rc * 8 + rr) * MD + i];
                    a0[rr] = fmaf(xv, w0v, a0[rr]);
                    a1[rr] = fmaf(xv, w1v, a1[rr]);
                }
            }
            #pragma unroll
            for (int rr = 0; rr < 8; rr++) {
                st1[(rc * 8 + rr) * FF1 + c0] = gelu_exact(a0[rr]);
                st1[(rc * 8 + rr) * FF1 + c1] = gelu_exact(a1[rr]);
            }
        }
    }
    __syncthreads();

    // ---- stage 2: T2 = gelu(T1 @ fw2 + fb2)  (dominant: 64x256x512)
    // thread tile 8 rows x 8 cols: 8 broadcast LDS + 8 coalesced LDG per 64 FMA
    {
        const int rt = tid >> 5, lane = tid & 31;
        float acc[8][8];
        #pragma unroll
        for (int jj = 0; jj < 8; jj++) {
            const float bv = fb2[lane + 32 * jj];
            #pragma unroll
            for (int rr = 0; rr < 8; rr++) acc[rr][jj] = bv;
        }
        for (int i = 0; i < FF1; i++) {
            float wv[8];
            #pragma unroll
            for (int jj = 0; jj < 8; jj++) wv[jj] = fw2[i * FF2 + lane + 32 * jj];
            #pragma unroll
            for (int rr = 0; rr < 8; rr++) {
                const float tv = st1[(rt * 8 + rr) * FF1 + i];
                #pragma unroll
                for (int jj = 0; jj < 8; jj++)
                    acc[rr][jj] = fmaf(tv, wv[jj], acc[rr][jj]);
            }
        }
        #pragma unroll
        for (int rr = 0; rr < 8; rr++)
            #pragma unroll
            for (int jj = 0; jj < 8; jj++)
                st2[(rt * 8 + rr) * FF2 + lane + 32 * jj] = gelu_exact(acc[rr][jj]);
    }
    __syncthreads();

    // ---- stage 3: T3 = T2 @ fw3 + fb3, + residual, store learn channels
    {
        const int rt = tid >> 5, c = tid & 31;
        float acc[8];
        const float bb = fb3[c];
        #pragma unroll
        for (int rr = 0; rr < 8; rr++) acc[rr] = bb;
        for (int i = 0; i < FF2; i++) {
            const float wv = fw3[i * LD + c];
            #pragma unroll
            for (int rr = 0; rr < 8; rr++)
                acc[rr] = fmaf(st2[(rt * 8 + rr) * FF2 + i], wv, acc[rr]);
        }
        #pragma unroll
        for (int rr = 0; rr < 8; rr++) {
            const long pi = r0 + rt * 8 + rr;
            out[pi * MD + c] = acc[rr] + sin_[(rt * 8 + rr) * MD + c];
        }
    }
}

extern "C" void kernel_launch(void* const* d_in, const int* in_sizes, int n_in,
                              void* d_out, int out_size) {
    const float* x   = (const float*)d_in[0];
    const float* psi = (const float*)d_in[1];
    const float* dw  = (const float*)d_in[2];
    const float* db  = (const float*)d_in[3];
    const float* hw1 = (const float*)d_in[4];
    const float* hb1 = (const float*)d_in[5];
    const float* hw2 = (const float*)d_in[6];
    const float* hb2 = (const float*)d_in[7];
    const float* fw1 = (const float*)d_in[8];
    const float* fb1 = (const float*)d_in[9];
    const float* fw2 = (const float*)d_in[10];
    const float* fb2 = (const float*)d_in[11];
    const float* fw3 = (const float*)d_in[12];
    const float* fb3 = (const float*)d_in[13];
    float* out = (float*)d_out;

    const size_t smA = SMEM_A_F * sizeof(float);
    const size_t smB = SMEM_B_F * sizeof(float);
    cudaFuncSetAttribute(disco_head_kernel,
                         cudaFuncAttributeMaxDynamicSharedMemorySize, (int)smA);
    cudaFuncSetAttribute(ffn_kernel,
                         cudaFuncAttributeMaxDynamicSharedMemorySize, (int)smB);

    dim3 gA(W / TW, H, B);
    disco_head_kernel<<<gA, TA, smA>>>(x, psi, dw, db, hw1, hb1, hw2, hb2, out);
    ffn_kernel<<<(B * H * W) / ROWS, TB, smB>>>(fw1, fb1, fw2, fb2, fw3, fb3, out);
}

// round 2
// speedup vs baseline: 1.5764x; 1.5764x over previous
#include <cuda_runtime.h>

namespace {
constexpr int B = 2, H = 128, W = 256, MD = 34, LD = 32;
constexpr int NH = 4, SH = 64, K = 25, P = 7, R = 3;
constexpr int FF1 = 512, FF2 = 256;
constexpr int PP = P * P; // 49
constexpr long M_PIX = (long)B * H * W; // 65536

// ---------------- Kernel A (disco + head MLP + residual) config ----------------
constexpr int TW   = 32;
constexpr int PIX  = 8;
constexpr int NGRP = TW / PIX;
constexpr int TA   = 512;
constexpr int XCOLS = TW + 2 * R; // 38

constexpr int OFF_WEFF = 0;
constexpr int OFF_SX   = OFF_WEFF + SH * PP;
constexpr int OFF_SD   = OFF_SX + LD * P * XCOLS;
constexpr int OFF_HW1  = OFF_SD + PIX * LD * 65;
constexpr int OFF_RED  = OFF_HW1 + SH * 32 * NH;
constexpr int OFF_HB1  = OFF_RED + 16 * PIX * 32;
constexpr int OFF_HW2  = OFF_HB1 + NH * 32;
constexpr int OFF_HB2  = OFF_HW2 + NH * 32;
constexpr int OFF_DB   = OFF_HB2 + NH;
constexpr int SMEM_A_F = OFF_DB + SH;

__device__ __forceinline__ float gelu_exact(float v) {
    return 0.5f * v * (1.0f + erff(v * 0.70710678118654752440f));
}

__device__ __forceinline__ unsigned f2tf(float f) {
    unsigned u;
    asm("cvt.rna.tf32.f32 %0, %1;" : "=r"(u) : "f"(f));
    return u;
}

__device__ __forceinline__ void mma_tf32(float c[4], const float4& a, const float2& b) {
    const unsigned* A = reinterpret_cast<const unsigned*>(&a);
    const unsigned* Bv = reinterpret_cast<const unsigned*>(&b);
    asm volatile(
        "mma.sync.aligned.m16n8k8.row.col.f32.tf32.tf32.f32 "
        "{%0,%1,%2,%3},{%4,%5,%6,%7},{%8,%9},{%0,%1,%2,%3};\n"
        : "+f"(c[0]), "+f"(c[1]), "+f"(c[2]), "+f"(c[3])
        : "r"(A[0]), "r"(A[1]), "r"(A[2]), "r"(A[3]), "r"(Bv[0]), "r"(Bv[1]));
}
} // namespace

// FFN intermediates (device-global scratch; no runtime allocation)
__device__ float g_t1[M_PIX * FF1]; // 128 MB
__device__ float g_t2[M_PIX * FF2]; //  64 MB

// =====================================================================
// Kernel A: DISCO conv + head MLP + residual (unchanged from R1 pass)
// =====================================================================
__global__ __launch_bounds__(TA) void disco_head_kernel(
    const float* __restrict__ x,   const float* __restrict__ psi,
    const float* __restrict__ dw,  const float* __restrict__ db,
    const float* __restrict__ hw1, const float* __restrict__ hb1,
    const float* __restrict__ hw2, const float* __restrict__ hb2,
    float* __restrict__ out)
{
    extern __shared__ float sm[];
    float* weff = sm + OFF_WEFF;
    float* sx   = sm + OFF_SX;
    float* sd   = sm + OFF_SD;
    float* shw1 = sm + OFF_HW1;
    float* sred = sm + OFF_RED;
    float* shb1 = sm + OFF_HB1;
    float* shw2 = sm + OFF_HW2;
    float* shb2 = sm + OFF_HB2;
    float* sdb  = sm + OFF_DB;

    const int tid = threadIdx.x;
    const int w0  = blockIdx.x * TW;
    const int h   = blockIdx.y;
    const int b   = blockIdx.z;

    for (int i = tid; i < NH * SH * 32; i += TA) {
        int o = i & 31; int s = (i >> 5) & 63; int n = i >> 11;
        shw1[(s * 32 + o) * NH + n] = hw1[i];
    }
    for (int i = tid; i < NH * 32; i += TA) { shb1[i] = hb1[i]; shw2[i] = hw2[i]; }
    if (tid < NH) shb2[tid] = hb2[tid];
    if (tid < SH) sdb[tid]  = db[tid];

    for (int i = tid; i < SH * PP; i += TA) {
        int f = i / PP, p = i % PP;
        float acc = 0.f;
        #pragma unroll
        for (int k = 0; k < K; k++)
            acc += dw[f * K + k] * psi[(k * H + h) * PP + p];
        weff[i] = acc;
    }

    for (int i = tid; i < LD * P * XCOLS; i += TA) {
        int ld = i & 31; int pos = i >> 5;
        int r = pos / XCOLS, c = pos % XCOLS;
        int lat = h + r - R; lat = lat < 0 ? 0 : (lat > H - 1 ? H - 1 : lat);
        int lon = (w0 + c - R + W) & (W - 1);
        sx[(ld * P + r) * XCOLS + c] = x[((b * H + lat) * W + lon) * MD + ld];
    }

    for (int i = tid; i < TW * 2; i += TA) {
        int px = i >> 1, j = i & 1;
        int gi = ((b * H + h) * W + (w0 + px)) * MD + LD + j;
        out[gi] = x[gi];
    }
    __syncthreads();

    for (int g = 0; g < NGRP; g++) {
        const int pxb = g * PIX;
        {
            const int sg  = tid >> 8;
            const int pr  = tid & 255;
            const int pix = pr >> 5, ld = pr & 31;
            float xr[PP];
            #pragma unroll
            for (int r = 0; r < P; r++)
                #pragma unroll
                for (int cc = 0; cc < P; cc++)
                    xr[r * P + cc] = sx[(ld * P + r) * XCOLS + (pxb + pix + cc)];
            #pragma unroll 4
            for (int si = 0; si < 32; si++) {
                const int s = sg * 32 + si;
                float acc = sdb[s];
                const float* wf = weff + s * PP;
                #pragma unroll
                for (int p = 0; p < PP; p++) acc = fmaf(wf[p], xr[p], acc);
                sd[pr * 65 + s] = acc;
            }
        }
        __syncthreads();
        {
            const int wp = tid >> 5, lane = tid & 31;
            const int o0 = 2 * wp, o1 = 2 * wp + 1;
            const int n  = lane >> 3;
            float a0[PIX], a1[PIX];
            const float b0 = shb1[n * 32 + o0], b1 = shb1[n * 32 + o1];
            #pragma unroll
            for (int px = 0; px < PIX; px++) { a0[px] = b0; a1[px] = b1; }
            for (int s = 0; s < SH; s++) {
                const float w0v = shw1[(s * 32 + o0) * NH + n];
                const float w1v = shw1[(s * 32 + o1) * NH + n];
                #pragma unroll
                for (int px = 0; px < PIX; px++) {
                    const float dv = sd[(px * 32 + lane) * 65 + s];
                    a0[px] = fmaf(dv, w0v, a0[px]);
                    a1[px] = fmaf(dv, w1v, a1[px]);
                }
            }
            const float h2a = shw2[n * 32 + o0], h2b = shw2[n * 32 + o1];
            #pragma unroll
            for (int px = 0; px < PIX; px++) {
                float v = gelu_exact(a0[px]) * h2a + gelu_exact(a1[px]) * h2b;
                sred[(wp * PIX + px) * 32 + lane] = v;
            }
        }
        __syncthreads();
        if (tid < PIX * 32) {
            const int px = tid >> 5, ld = tid & 31;
            float acc = 0.f;
            #pragma unroll
            for (int wp = 0; wp < 16; wp++) acc += sred[(wp * PIX + px) * 32 + ld];
            const int n = ld >> 3;
            acc += shb2[n] + sx[(ld * P + R) * XCOLS + (pxb + px + R)];
            out[((b * H + h) * W + (w0 + pxb + px)) * MD + ld] = acc;
        }
        __syncthreads();
    }
}

// =====================================================================
// FFN stage 1: t1 = gelu(out[:, :34] @ fw1 + fb1)   [M,34]x[34,512]
// K padded 34->40 (5 k8 steps). MT=64, NT=128, 8 warps (2m x 4n).
// =====================================================================
namespace {
constexpr int S1_A = 4 * 5 * 128;   // 2560 floats
constexpr int S1_B = 16 * 5 * 64;   // 5120 floats
}
__global__ __launch_bounds__(256) void ffn_s1(
    const float* __restrict__ xin, const float* __restrict__ fw1,
    const float* __restrict__ fb1)
{
    extern __shared__ float sm[];
    float* sA = sm;
    float* sB = sm + S1_A;
    const int tid = threadIdx.x, lane = tid & 31, w = tid >> 5;
    const int mw = w >> 2, nw = w & 3;
    const long r0 = (long)blockIdx.x * 64;
    const int  n0 = blockIdx.y * 128;

    for (int e = tid; e < 64 * 40; e += 256) {
        int r = e / 40, k = e % 40;
        float v = (k < MD) ? xin[(r0 + r) * MD + k] : 0.f;
        int mt = r >> 4, rr = r & 15, ks = k >> 3, kk = k & 7;
        int ln = (rr & 7) * 4 + (kk & 3), rg = (rr >> 3) + ((kk >> 2) << 1);
        sA[((mt * 5 + ks) * 32 + ln) * 4 + rg] = __uint_as_float(f2tf(v));
    }
    for (int e = tid; e < 40 * 128; e += 256) {
        int k = e >> 7, n = e & 127;
        float v = (k < MD) ? fw1[k * FF1 + n0 + n] : 0.f;
        int nt = n >> 3, g = n & 7, ks = k >> 3, kk = k & 7;
        sB[((nt * 5 + ks) * 32 + g * 4 + (kk & 3)) * 2 + (kk >> 2)] =
            __uint_as_float(f2tf(v));
    }
    __syncthreads();

    float c[2][4][4] = {};
    #pragma unroll
    for (int ks = 0; ks < 5; ks++) {
        float4 a[2]; float2 b[4];
        #pragma unroll
        for (int mi = 0; mi < 2; mi++)
            a[mi] = reinterpret_cast<const float4*>(sA)[((mw * 2 + mi) * 5 + ks) * 32 + lane];
        #pragma unroll
        for (int ni = 0; ni < 4; ni++)
            b[ni] = reinterpret_cast<const float2*>(sB)[((nw * 4 + ni) * 5 + ks) * 32 + lane];
        #pragma unroll
        for (int mi = 0; mi < 2; mi++)
            #pragma unroll
            for (int ni = 0; ni < 4; ni++)
                mma_tf32(c[mi][ni], a[mi], b[ni]);
    }

    const int g = lane >> 2, tg = lane & 3;
    #pragma unroll
    for (int mi = 0; mi < 2; mi++) {
        const long rr = r0 + mw * 32 + mi * 16 + g;
        #pragma unroll
        for (int ni = 0; ni < 4; ni++) {
            const int col = n0 + nw * 32 + ni * 8 + tg * 2;
            const float b0 = fb1[col], b1 = fb1[col + 1];
            g_t1[rr * FF1 + col]           = gelu_exact(c[mi][ni][0] + b0);
            g_t1[rr * FF1 + col + 1]       = gelu_exact(c[mi][ni][1] + b1);
            g_t1[(rr + 8) * FF1 + col]     = gelu_exact(c[mi][ni][2] + b0);
            g_t1[(rr + 8) * FF1 + col + 1] = gelu_exact(c[mi][ni][3] + b1);
        }
    }
}

// =====================================================================
// FFN stage 2: t2 = gelu(t1 @ fw2 + fb2)   [M,512]x[512,256]  (dominant)
// MT=64, NT=128, KC=32 (4 k8 steps), 16 chunks, double-buffered.
// =====================================================================
namespace {
constexpr int S2_A = 4 * 4 * 128;    // 2048
constexpr int S2_B = 16 * 4 * 64;    // 4096
constexpr int S2_BUF = S2_A + S2_B;  // 6144 floats per buffer
}
__global__ __launch_bounds__(256) void ffn_s2(
    const float* __restrict__ fw2, const float* __restrict__ fb2)
{
    extern __shared__ float sm[];
    const int tid = threadIdx.x, lane = tid & 31, w = tid >> 5;
    const int mw = w >> 2, nw = w & 3;
    const long r0 = (long)blockIdx.x * 64;
    const int  n0 = blockIdx.y * 128;

    float c[2][4][4] = {};

    for (int kc = 0; kc < 16; kc++) {
        float* sA = sm + (kc & 1) * S2_BUF;
        float* sB = sA + S2_A;
        const int k0 = kc * 32;
        #pragma unroll
        for (int i = 0; i < 8; i++) {
            int e = tid + i * 256;
            int r = e >> 5, k = e & 31;
            float v = g_t1[(r0 + r) * FF1 + k0 + k];
            int mt = r >> 4, rr = r & 15, ks = k >> 3, kk = k & 7;
            int ln = (rr & 7) * 4 + (kk & 3), rg = (rr >> 3) + ((kk >> 2) << 1);
            sA[((mt * 4 + ks) * 32 + ln) * 4 + rg] = __uint_as_float(f2tf(v));
        }
        #pragma unroll
        for (int i = 0; i < 16; i++) {
            int e = tid + i * 256;
            int k = e >> 7, n = e & 127;
            float v = fw2[(k0 + k) * FF2 + n0 + n];
            int nt = n >> 3, g = n & 7, kk = k & 7, ks = k >> 3;
            sB[((nt * 4 + ks) * 32 + g * 4 + (kk & 3)) * 2 + (kk >> 2)] =
                __uint_as_float(f2tf(v));
        }
        __syncthreads();
        #pragma unroll
        for (int ks = 0; ks < 4; ks++) {
            float4 a[2]; float2 b[4];
            #pragma unroll
            for (int mi = 0; mi < 2; mi++)
                a[mi] = reinterpret_cast<const float4*>(sA)[((mw * 2 + mi) * 4 + ks) * 32 + lane];
            #pragma unroll
            for (int ni = 0; ni < 4; ni++)
                b[ni] = reinterpret_cast<const float2*>(sB)[((nw * 4 + ni) * 4 + ks) * 32 + lane];
            #pragma unroll
            for (int mi = 0; mi < 2; mi++)
                #pragma unroll
                for (int ni = 0; ni < 4; ni++)
                    mma_tf32(c[mi][ni], a[mi], b[ni]);
        }
        __syncthreads();
    }

    const int g = lane >> 2, tg = lane & 3;
    #pragma unroll
    for (int mi = 0; mi < 2; mi++) {
        const long rr = r0 + mw * 32 + mi * 16 + g;
        #pragma unroll
        for (int ni = 0; ni < 4; ni++) {
            const int col = n0 + nw * 32 + ni * 8 + tg * 2;
            const float b0 = fb2[col], b1 = fb2[col + 1];
            g_t2[rr * FF2 + col]           = gelu_exact(c[mi][ni][0] + b0);
            g_t2[rr * FF2 + col + 1]       = gelu_exact(c[mi][ni][1] + b1);
            g_t2[(rr + 8) * FF2 + col]     = gelu_exact(c[mi][ni][2] + b0);
            g_t2[(rr + 8) * FF2 + col + 1] = gelu_exact(c[mi][ni][3] + b1);
        }
    }
}

// =====================================================================
// FFN stage 3: out[:, :32] = t2 @ fw3 + fb3 + out[:, :32]   [M,256]x[256,32]
// MT=128 (8 warps x m16), N=32 (4 n8 per warp), B staged fully (32 ks).
// =====================================================================
namespace {
constexpr int S3_B = 4 * 32 * 64;    // 8192 floats (full fw3)
constexpr int S3_A = 8 * 4 * 128;    // 4096 per buffer
}
__global__ __launch_bounds__(256) void ffn_s3(
    const float* __restrict__ fw3, const float* __restrict__ fb3,
    float* __restrict__ out)
{
    extern __shared__ float sm[];
    float* sB = sm;
    const int tid = threadIdx.x, lane = tid & 31, w = tid >> 5;
    const long r0 = (long)blockIdx.x * 128;

    for (int e = tid; e < 256 * 32; e += 256) {
        int k = e >> 5, n = e & 31;
        float v = fw3[k * LD + n];
        int nt = n >> 3, g = n & 7, ks = k >> 3, kk = k & 7;
        sB[((nt * 32 + ks) * 32 + g * 4 + (kk & 3)) * 2 + (kk >> 2)] =
            __uint_as_float(f2tf(v));
    }

    float c[4][4] = {};
    for (int kc = 0; kc < 8; kc++) {
        float* sA = sm + S3_B + (kc & 1) * S3_A;
        const int k0 = kc * 32;
        #pragma unroll
        for (int i = 0; i < 16; i++) {
            int e = tid + i * 256;
            int r = e >> 5, k = e & 31;
            float v = g_t2[(r0 + r) * FF2 + k0 + k];
            int mt = r >> 4, rr = r & 15, ks = k >> 3, kk = k & 7;
            int ln = (rr & 7) * 4 + (kk & 3), rg = (rr >> 3) + ((kk >> 2) << 1);
            sA[((mt * 4 + ks) * 32 + ln) * 4 + rg] = __uint_as_float(f2tf(v));
        }
        __syncthreads();
        #pragma unroll
        for (int ks = 0; ks < 4; ks++) {
            float4 a = reinterpret_cast<const float4*>(sA)[(w * 4 + ks) * 32 + lane];
            #pragma unroll
            for (int ni = 0; ni < 4; ni++) {
                float2 b = reinterpret_cast<const float2*>(sB)[((ni * 32 + kc * 4 + ks)) * 32 + lane];
                mma_tf32(c[ni], a, b);
            }
        }
        __syncthreads();
    }

    const int g = lane >> 2, tg = lane & 3;
    const long rlo = r0 + w * 16 + g, rhi = rlo + 8;
    #pragma unroll
    for (int ni = 0; ni < 4; ni++) {
        const int col = ni * 8 + tg * 2;
        const float b0 = fb3[col], b1 = fb3[col + 1];
        out[rlo * MD + col]     += c[ni][0] + b0;
        out[rlo * MD + col + 1] += c[ni][1] + b1;
        out[rhi * MD + col]     += c[ni][2] + b0;
        out[rhi * MD + col + 1] += c[ni][3] + b1;
    }
}

extern "C" void kernel_launch(void* const* d_in, const int* in_sizes, int n_in,
                              void* d_out, int out_size) {
    const float* x   = (const float*)d_in[0];
    const float* psi = (const float*)d_in[1];
    const float* dw  = (const float*)d_in[2];
    const float* db  = (const float*)d_in[3];
    const float* hw1 = (const float*)d_in[4];
    const float* hb1 = (const float*)d_in[5];
    const float* hw2 = (const float*)d_in[6];
    const float* hb2 = (const float*)d_in[7];
    const float* fw1 = (const float*)d_in[8];
    const float* fb1 = (const float*)d_in[9];
    const float* fw2 = (const float*)d_in[10];
    const float* fb2 = (const float*)d_in[11];
    const float* fw3 = (const float*)d_in[12];
    const float* fb3 = (const float*)d_in[13];
    float* out = (float*)d_out;

    const size_t smA  = SMEM_A_F * sizeof(float);
    const size_t sm1  = (S1_A + S1_B) * sizeof(float);
    const size_t sm2  = 2 * S2_BUF * sizeof(float);
    const size_t sm3  = (S3_B + 2 * S3_A) * sizeof(float);
    cudaFuncSetAttribute(disco_head_kernel, cudaFuncAttributeMaxDynamicSharedMemorySize, (int)smA);
    cudaFuncSetAttribute(ffn_s1, cudaFuncAttributeMaxDynamicSharedMemorySize, (int)sm1);
    cudaFuncSetAttribute(ffn_s2, cudaFuncAttributeMaxDynamicSharedMemorySize, (int)sm2);
    cudaFuncSetAttribute(ffn_s3, cudaFuncAttributeMaxDynamicSharedMemorySize, (int)sm3);

    dim3 gA(W / TW, H, B);
    disco_head_kernel<<<gA, TA, smA>>>(x, psi, dw, db, hw1, hb1, hw2, hb2, out);
    ffn_s1<<<dim3((unsigned)(M_PIX / 64), 4), 256, sm1>>>(out, fw1, fb1);
    ffn_s2<<<dim3((unsigned)(M_PIX / 64), 2), 256, sm2>>>(fw2, fb2);
    ffn_s3<<<dim3((unsigned)(M_PIX / 128)), 256, sm3>>>(fw3, fb3, out);
}

// round 4
// speedup vs baseline: 2.8715x; 1.8216x over previous
#include <cuda_runtime.h>

namespace {
constexpr int B = 2, H = 128, W = 256, MD = 34, LD = 32;
constexpr int NH = 4, SH = 64, K = 25, P = 7, R = 3;
constexpr int FF1 = 512, FF2 = 256;
constexpr int PP = P * P; // 49
constexpr long M_PIX = (long)B * H * W; // 65536

// ---------------- disco mma kernel config ----------------
constexpr int TW   = 32;            // longitude pixels per block
constexpr int PIX  = 8;             // pixels per group (16 m16 tiles = 256 rows)
constexpr int NGRP = TW / PIX;      // 4
constexpr int TA   = 512;           // 16 warps
constexpr int XCOLS = TW + 2 * R;   // 38

constexpr int WEFFB_F = 8 * 7 * 32 * 2;      // 3584 floats per latitude
constexpr int HW1B_F  = 4 * 4 * 8 * 32 * 2;  // 8192 floats

// smem offsets (floats)
constexpr int OFF_SX   = 0;                       // 8512
constexpr int OFF_SWB  = OFF_SX + LD * P * XCOLS; // 3584
constexpr int OFF_HW1B = OFF_SWB + WEFFB_F;       // 8192
constexpr int OFF_SDA  = OFF_HW1B + HW1B_F;       // 16*8*32*4 = 16384
constexpr int OFF_SDB  = OFF_SDA + 16 * 8 * 32 * 4; // 64
constexpr int OFF_HB1  = OFF_SDB + SH;            // 128
constexpr int OFF_HW2  = OFF_HB1 + NH * 32;       // 128
constexpr int OFF_HB2  = OFF_HW2 + NH * 32;       // 4
constexpr int SMEM_D_F = OFF_HB2 + NH;

__device__ __forceinline__ float gelu_exact(float v) {
    return 0.5f * v * (1.0f + erff(v * 0.70710678118654752440f));
}

__device__ __forceinline__ unsigned f2tf(float f) {
    unsigned u;
    asm("cvt.rna.tf32.f32 %0, %1;" : "=r"(u) : "f"(f));
    return u;
}
__device__ __forceinline__ float f2tf_f(float f) { return __uint_as_float(f2tf(f)); }

__device__ __forceinline__ void mma_tf32(float c[4], const float4& a, const float2& b) {
    const unsigned* A = reinterpret_cast<const unsigned*>(&a);
    const unsigned* Bv = reinterpret_cast<const unsigned*>(&b);
    asm volatile(
        "mma.sync.aligned.m16n8k8.row.col.f32.tf32.tf32.f32 "
        "{%0,%1,%2,%3},{%4,%5,%6,%7},{%8,%9},{%0,%1,%2,%3};\n"
        : "+f"(c[0]), "+f"(c[1]), "+f"(c[2]), "+f"(c[3])
        : "r"(A[0]), "r"(A[1]), "r"(A[2]), "r"(A[3]), "r"(Bv[0]), "r"(Bv[1]));
}
} // namespace

// device-global scratch (no runtime allocation)
__device__ float g_t1[M_PIX * FF1];        // 128 MB
__device__ float g_t2[M_PIX * FF2];        //  64 MB
__device__ float g_weffB[H * WEFFB_F];     // 1.75 MB (B-frag layout, tf32 bits)
__device__ float g_hw1B[HW1B_F];           // 32 KB  (B-frag layout, tf32 bits)

// =====================================================================
// prep: fold psi into disco_w per latitude, store in mma B-frag layout
// =====================================================================
__global__ void prep_weffB(const float* __restrict__ dw,
                           const float* __restrict__ psi) {
    const int h = blockIdx.x;
    for (int e = threadIdx.x; e < WEFFB_F; e += blockDim.x) {
        int half = e & 1, t = e >> 1;
        int lane = t & 31; t >>= 5;
        int ks = t % 7, nt = t / 7;
        int g = lane >> 2, tg = lane & 3;
        int p = ks * 8 + tg + 4 * half;
        int s = nt * 8 + g;
        float acc = 0.f;
        if (p < PP) {
            #pragma unroll
            for (int k = 0; k < K; k++)
                acc += dw[s * K + k] * psi[(k * H + h) * PP + p];
        }
        g_weffB[h * WEFFB_F + e] = f2tf_f(acc);
    }
}

__global__ void prep_hw1B(const float* __restrict__ hw1) {
    int e = blockIdx.x * blockDim.x + threadIdx.x;
    if (e >= HW1B_F) return;
    int half = e & 1, t = e >> 1;
    int lane = t & 31; t >>= 5;
    int ks = t & 7; t >>= 3;
    int nt = t & 3; int n = t >> 2;
    int g = lane >> 2, tg = lane & 3;
    int s = ks * 8 + tg + 4 * half;
    int o = nt * 8 + g;
    g_hw1B[e] = f2tf_f(hw1[(n * SH + s) * 32 + o]);
}

// =====================================================================
// disco conv + head MLP + residual, tf32 mma, warp-private intermediate
// =====================================================================
__global__ __launch_bounds__(TA) void disco_head_mma(
    const float* __restrict__ x,   const float* __restrict__ db,
    const float* __restrict__ hb1, const float* __restrict__ hw2,
    const float* __restrict__ hb2, float* __restrict__ out)
{
    extern __shared__ float sm[];
    float* sx    = sm + OFF_SX;
    float* swB   = sm + OFF_SWB;
    float* shw1b = sm + OFF_HW1B;
    float* sdb   = sm + OFF_SDB;
    float* shb1  = sm + OFF_HB1;
    float* shw2  = sm + OFF_HW2;
    float* shb2  = sm + OFF_HB2;

    const int tid = threadIdx.x;
    const int lane = tid & 31, mt = tid >> 5;
    const int g  = lane >> 2, tg = lane & 3;
    const int w0 = blockIdx.x * TW;
    const int h  = blockIdx.y;
    const int b  = blockIdx.z;

    // ---- stage fragments + small vectors
    for (int e = tid; e < WEFFB_F; e += TA) swB[e] = g_weffB[h * WEFFB_F + e];
    for (int e = tid; e < HW1B_F; e += TA)  shw1b[e] = g_hw1B[e];
    if (tid < SH) sdb[tid] = db[tid];
    if (tid < NH * 32) { shb1[tid] = hb1[tid]; shw2[tid] = hw2[tid]; }
    if (tid < NH) shb2[tid] = hb2[tid];

    // ---- stencil tile: 32 ch x 7 lat rows (clamped) x 38 lon (wrapped)
    for (int i = tid; i < LD * P * XCOLS; i += TA) {
        int ld = i & 31; int pos = i >> 5;
        int r = pos / XCOLS, c = pos % XCOLS;
        int lat = h + r - R; lat = lat < 0 ? 0 : (lat > H - 1 ? H - 1 : lat);
        int lon = (w0 + c - R + W) & (W - 1);
        sx[(ld * P + r) * XCOLS + c] = x[((b * H + lat) * W + lon) * MD + ld];
    }
    // ---- sin_cos passthrough
    for (int i = tid; i < TW * 2; i += TA) {
        int px = i >> 1, j = i & 1;
        int gi = ((b * H + h) * W + (w0 + px)) * MD + LD + j;
        out[gi] = x[gi];
    }
    __syncthreads();

    // row mapping (head-major): m = mt*16 + r16; n = mt>>2;
    // ldh = (mt&3)*2 + (r16>>3); ld = n*8+ldh; px = r16&7 (= g)
    const int nh  = mt >> 2;
    const int ld0 = nh * 8 + (mt & 3) * 2;  // rows r16 < 8
    const int ld1 = ld0 + 1;                // rows r16 >= 8
    const int px  = g;
    float* sdAw = sm + OFF_SDA + mt * (8 * 32 * 4); // warp-private

    const float2* swB2   = reinterpret_cast<const float2*>(swB);
    const float2* hw1b2  = reinterpret_cast<const float2*>(shw1b);
    const float4* sdA4   = reinterpret_cast<const float4*>(sm + OFF_SDA);

    for (int grp = 0; grp < NGRP; grp++) {
        const int cbase = grp * PIX + px;

        // ======= phase 1: d = A(taps) @ weff, M=16/warp, N=64, K=56 =======
        float c1[8][4] = {};
        #pragma unroll
        for (int ks = 0; ks < 7; ks++) {
            const int p0 = ks * 8 + tg, p1 = p0 + 4;
            float4 a;
            {
                int r = p0 / 7, cc = p0 % 7;
                float v0 = (p0 < PP) ? sx[(ld0 * P + r) * XCOLS + cbase + cc] : 0.f;
                float v1 = (p0 < PP) ? sx[(ld1 * P + r) * XCOLS + cbase + cc] : 0.f;
                a.x = f2tf_f(v0); a.y = f2tf_f(v1);
            }
            {
                int r = p1 / 7, cc = p1 % 7;
                float v0 = (p1 < PP) ? sx[(ld0 * P + r) * XCOLS + cbase + cc] : 0.f;
                float v1 = (p1 < PP) ? sx[(ld1 * P + r) * XCOLS + cbase + cc] : 0.f;
                a.z = f2tf_f(v0); a.w = f2tf_f(v1);
            }
            #pragma unroll
            for (int nt = 0; nt < 8; nt++) {
                float2 bb = swB2[(nt * 7 + ks) * 32 + lane];
                mma_tf32(c1[nt], a, bb);
            }
        }

        // ---- epilogue 1: +bias, cvt, scatter into A-frag layout (warp-private)
        #pragma unroll
        for (int nt = 0; nt < 8; nt++) {
            const int kk0 = 2 * tg, kk1 = kk0 + 1;
            const float b0 = sdb[nt * 8 + kk0], b1 = sdb[nt * 8 + kk1];
            const int i0 = (nt * 32 + g * 4 + (kk0 & 3)) * 4 + ((kk0 >> 2) << 1);
            const int i1 = (nt * 32 + g * 4 + (kk1 & 3)) * 4 + ((kk1 >> 2) << 1);
            sdAw[i0]     = f2tf_f(c1[nt][0] + b0);
            sdAw[i1]     = f2tf_f(c1[nt][1] + b1);
            sdAw[i0 + 1] = f2tf_f(c1[nt][2] + b0);
            sdAw[i1 + 1] = f2tf_f(c1[nt][3] + b1);
        }
        __syncwarp();

        // ======= phase 2: h = d @ hw1[n], M=16, N=32, K=64 =======
        float c2[4][4] = {};
        #pragma unroll
        for (int ks = 0; ks < 8; ks++) {
            float4 a = sdA4[(mt * 8 + ks) * 32 + lane];
            #pragma unroll
            for (int nt2 = 0; nt2 < 4; nt2++) {
                float2 bb = hw1b2[((nh * 4 + nt2) * 8 + ks) * 32 + lane];
                mma_tf32(c2[nt2], a, bb);
            }
        }

        // ---- epilogue 2: gelu + hw2 dot + cross-lane reduce + residual
        float part0 = 0.f, part1 = 0.f;
        #pragma unroll
        for (int nt2 = 0; nt2 < 4; nt2++) {
            const int o0 = nt2 * 8 + 2 * tg, o1 = o0 + 1;
            const float w0v = shw2[nh * 32 + o0], w1v = shw2[nh * 32 + o1];
            const float bb0 = shb1[nh * 32 + o0], bb1 = shb1[nh * 32 + o1];
            part0 += gelu_exact(c2[nt2][0] + bb0) * w0v
                   + gelu_exact(c2[nt2][1] + bb1) * w1v;
            part1 += gelu_exact(c2[nt2][2] + bb0) * w0v
                   + gelu_exact(c2[nt2][3] + bb1) * w1v;
        }
        part0 += __shfl_xor_sync(0xffffffffu, part0, 1);
        part0 += __shfl_xor_sync(0xffffffffu, part0, 2);
        part1 += __shfl_xor_sync(0xffffffffu, part1, 1);
        part1 += __shfl_xor_sync(0xffffffffu, part1, 2);
        if (tg == 0) {
            const float v0 = part0 + shb2[nh] + sx[(ld0 * P + R) * XCOLS + cbase + R];
            const float v1 = part1 + shb2[nh] + sx[(ld1 * P + R) * XCOLS + cbase + R];
            const long o = ((long)(b * H + h) * W + w0 + grp * PIX + px) * MD;
            out[o + ld0] = v0;
            out[o + ld1] = v1;
        }
        __syncwarp();
    }
}

// =====================================================================
// FFN stage 1: t1 = gelu(out[:, :34] @ fw1 + fb1)   [M,34]x[34,512]
// =====================================================================
namespace {
constexpr int S1_A = 4 * 5 * 128;   // 2560 floats
constexpr int S1_B = 16 * 5 * 64;   // 5120 floats
}
__global__ __launch_bounds__(256) void ffn_s1(
    const float* __restrict__ xin, const float* __restrict__ fw1,
    const float* __restrict__ fb1)
{
    extern __shared__ float sm[];
    float* sA = sm;
    float* sB = sm + S1_A;
    const int tid = threadIdx.x, lane = tid & 31, w = tid >> 5;
    const int mw = w >> 2, nw = w & 3;
    const long r0 = (long)blockIdx.x * 64;
    const int  n0 = blockIdx.y * 128;

    for (int e = tid; e < 64 * 40; e += 256) {
        int r = e / 40, k = e % 40;
        float v = (k < MD) ? xin[(r0 + r) * MD + k] : 0.f;
        int mt = r >> 4, rr = r & 15, ks = k >> 3, kk = k & 7;
        int ln = (rr & 7) * 4 + (kk & 3), rg = (rr >> 3) + ((kk >> 2) << 1);
        sA[((mt * 5 + ks) * 32 + ln) * 4 + rg] = f2tf_f(v);
    }
    for (int e = tid; e < 40 * 128; e += 256) {
        int k = e >> 7, n = e & 127;
        float v = (k < MD) ? fw1[k * FF1 + n0 + n] : 0.f;
        int nt = n >> 3, g = n & 7, ks = k >> 3, kk = k & 7;
        sB[((nt * 5 + ks) * 32 + g * 4 + (kk & 3)) * 2 + (kk >> 2)] = f2tf_f(v);
    }
    __syncthreads();

    float c[2][4][4] = {};
    #pragma unroll
    for (int ks = 0; ks < 5; ks++) {
        float4 a[2]; float2 b[4];
        #pragma unroll
        for (int mi = 0; mi < 2; mi++)
            a[mi] = reinterpret_cast<const float4*>(sA)[((mw * 2 + mi) * 5 + ks) * 32 + lane];
        #pragma unroll
        for (int ni = 0; ni < 4; ni++)
            b[ni] = reinterpret_cast<const float2*>(sB)[((nw * 4 + ni) * 5 + ks) * 32 + lane];
        #pragma unroll
        for (int mi = 0; mi < 2; mi++)
            #pragma unroll
            for (int ni = 0; ni < 4; ni++)
                mma_tf32(c[mi][ni], a[mi], b[ni]);
    }

    const int g = lane >> 2, tg = lane & 3;
    #pragma unroll
    for (int mi = 0; mi < 2; mi++) {
        const long rr = r0 + mw * 32 + mi * 16 + g;
        #pragma unroll
        for (int ni = 0; ni < 4; ni++) {
            const int col = n0 + nw * 32 + ni * 8 + tg * 2;
            const float b0 = fb1[col], b1 = fb1[col + 1];
            g_t1[rr * FF1 + col]           = gelu_exact(c[mi][ni][0] + b0);
            g_t1[rr * FF1 + col + 1]       = gelu_exact(c[mi][ni][1] + b1);
            g_t1[(rr + 8) * FF1 + col]     = gelu_exact(c[mi][ni][2] + b0);
            g_t1[(rr + 8) * FF1 + col + 1] = gelu_exact(c[mi][ni][3] + b1);
        }
    }
}

// =====================================================================
// FFN stage 2: t2 = gelu(t1 @ fw2 + fb2)   [M,512]x[512,256]
// =====================================================================
namespace {
constexpr int S2_A = 4 * 4 * 128;    // 2048
constexpr int S2_B = 16 * 4 * 64;    // 4096
constexpr int S2_BUF = S2_A + S2_B;  // 6144 floats per buffer
}
__global__ __launch_bounds__(256) void ffn_s2(
    const float* __restrict__ fw2, const float* __restrict__ fb2)
{
    extern __shared__ float sm[];
    const int tid = threadIdx.x, lane = tid & 31, w = tid >> 5;
    const int mw = w >> 2, nw = w & 3;
    const long r0 = (long)blockIdx.x * 64;
    const int  n0 = blockIdx.y * 128;

    float c[2][4][4] = {};

    for (int kc = 0; kc < 16; kc++) {
        float* sA = sm + (kc & 1) * S2_BUF;
        float* sB = sA + S2_A;
        const int k0 = kc * 32;
        #pragma unroll
        for (int i = 0; i < 8; i++) {
            int e = tid + i * 256;
            int r = e >> 5, k = e & 31;
            float v = g_t1[(r0 + r) * FF1 + k0 + k];
            int mt = r >> 4, rr = r & 15, ks = k >> 3, kk = k & 7;
            int ln = (rr & 7) * 4 + (kk & 3), rg = (rr >> 3) + ((kk >> 2) << 1);
            sA[((mt * 4 + ks) * 32 + ln) * 4 + rg] = f2tf_f(v);
        }
        #pragma unroll
        for (int i = 0; i < 16; i++) {
            int e = tid + i * 256;
            int k = e >> 7, n = e & 127;
            float v = fw2[(k0 + k) * FF2 + n0 + n];
            int nt = n >> 3, g = n & 7, kk = k & 7, ks = k >> 3;
            sB[((nt * 4 + ks) * 32 + g * 4 + (kk & 3)) * 2 + (kk >> 2)] = f2tf_f(v);
        }
        __syncthreads();
        #pragma unroll
        for (int ks = 0; ks < 4; ks++) {
            float4 a[2]; float2 b[4];
            #pragma unroll
            for (int mi = 0; mi < 2; mi++)
                a[mi] = reinterpret_cast<const float4*>(sA)[((mw * 2 + mi) * 4 + ks) * 32 + lane];
            #pragma unroll
            for (int ni = 0; ni < 4; ni++)
                b[ni] = reinterpret_cast<const float2*>(sB)[((nw * 4 + ni) * 4 + ks) * 32 + lane];
            #pragma unroll
            for (int mi = 0; mi < 2; mi++)
                #pragma unroll
                for (int ni = 0; ni < 4; ni++)
                    mma_tf32(c[mi][ni], a[mi], b[ni]);
        }
        __syncthreads();
    }

    const int g = lane >> 2, tg = lane & 3;
    #pragma unroll
    for (int mi = 0; mi < 2; mi++) {
        const long rr = r0 + mw * 32 + mi * 16 + g;
        #pragma unroll
        for (int ni = 0; ni < 4; ni++) {
            const int col = n0 + nw * 32 + ni * 8 + tg * 2;
            const float b0 = fb2[col], b1 = fb2[col + 1];
            g_t2[rr * FF2 + col]           = gelu_exact(c[mi][ni][0] + b0);
            g_t2[rr * FF2 + col + 1]       = gelu_exact(c[mi][ni][1] + b1);
            g_t2[(rr + 8) * FF2 + col]     = gelu_exact(c[mi][ni][2] + b0);
            g_t2[(rr + 8) * FF2 + col + 1] = gelu_exact(c[mi][ni][3] + b1);
        }
    }
}

// =====================================================================
// FFN stage 3: out[:, :32] += t2 @ fw3 + fb3   [M,256]x[256,32]
// =====================================================================
namespace {
constexpr int S3_B = 4 * 32 * 64;    // 8192 floats (full fw3)
constexpr int S3_A = 8 * 4 * 128;    // 4096 per buffer
}
__global__ __launch_bounds__(256) void ffn_s3(
    const float* __restrict__ fw3, const float* __restrict__ fb3,
    float* __restrict__ out)
{
    extern __shared__ float sm[];
    float* sB = sm;
    const int tid = threadIdx.x, lane = tid & 31, w = tid >> 5;
    const long r0 = (long)blockIdx.x * 128;

    for (int e = tid; e < 256 * 32; e += 256) {
        int k = e >> 5, n = e & 31;
        float v = fw3[k * LD + n];
        int nt = n >> 3, g = n & 7, ks = k >> 3, kk = k & 7;
        sB[((nt * 32 + ks) * 32 + g * 4 + (kk & 3)) * 2 + (kk >> 2)] = f2tf_f(v);
    }

    float c[4][4] = {};
    for (int kc = 0; kc < 8; kc++) {
        float* sA = sm + S3_B + (kc & 1) * S3_A;
        const int k0 = kc * 32;
        #pragma unroll
        for (int i = 0; i < 16; i++) {
            int e = tid + i * 256;
            int r = e >> 5, k = e & 31;
            float v = g_t2[(r0 + r) * FF2 + k0 + k];
            int mt = r >> 4, rr = r & 15, ks = k >> 3, kk = k & 7;
            int ln = (rr & 7) * 4 + (kk & 3), rg = (rr >> 3) + ((kk >> 2) << 1);
            sA[((mt * 4 + ks) * 32 + ln) * 4 + rg] = f2tf_f(v);
        }
        __syncthreads();
        #pragma unroll
        for (int ks = 0; ks < 4; ks++) {
            float4 a = reinterpret_cast<const float4*>(sA)[(w * 4 + ks) * 32 + lane];
            #pragma unroll
            for (int ni = 0; ni < 4; ni++) {
                float2 b = reinterpret_cast<const float2*>(sB)[((ni * 32 + kc * 4 + ks)) * 32 + lane];
                mma_tf32(c[ni], a, b);
            }
        }
        __syncthreads();
    }

    const int g = lane >> 2, tg = lane & 3;
    const long rlo = r0 + w * 16 + g, rhi = rlo + 8;
    #pragma unroll
    for (int ni = 0; ni < 4; ni++) {
        const int col = ni * 8 + tg * 2;
        const float b0 = fb3[col], b1 = fb3[col + 1];
        out[rlo * MD + col]     += c[ni][0] + b0;
        out[rlo * MD + col + 1] += c[ni][1] + b1;
        out[rhi * MD + col]     += c[ni][2] + b0;
        out[rhi * MD + col + 1] += c[ni][3] + b1;
    }
}

extern "C" void kernel_launch(void* const* d_in, const int* in_sizes, int n_in,
                              void* d_out, int out_size) {
    const float* x   = (const float*)d_in[0];
    const float* psi = (const float*)d_in[1];
    const float* dw  = (const float*)d_in[2];
    const float* db  = (const float*)d_in[3];
    const float* hw1 = (const float*)d_in[4];
    const float* hb1 = (const float*)d_in[5];
    const float* hw2 = (const float*)d_in[6];
    const float* hb2 = (const float*)d_in[7];
    const float* fw1 = (const float*)d_in[8];
    const float* fb1 = (const float*)d_in[9];
    const float* fw2 = (const float*)d_in[10];
    const float* fb2 = (const float*)d_in[11];
    const float* fw3 = (const float*)d_in[12];
    const float* fb3 = (const float*)d_in[13];
    float* out = (float*)d_out;

    const size_t smD = SMEM_D_F * sizeof(float);
    const size_t sm1 = (S1_A + S1_B) * sizeof(float);
    const size_t sm2 = 2 * S2_BUF * sizeof(float);
    const size_t sm3 = (S3_B + 2 * S3_A) * sizeof(float);
    cudaFuncSetAttribute(disco_head_mma, cudaFuncAttributeMaxDynamicSharedMemorySize, (int)smD);
    cudaFuncSetAttribute(ffn_s1, cudaFuncAttributeMaxDynamicSharedMemorySize, (int)sm1);
    cudaFuncSetAttribute(ffn_s2, cudaFuncAttributeMaxDynamicSharedMemorySize, (int)sm2);
    cudaFuncSetAttribute(ffn_s3, cudaFuncAttributeMaxDynamicSharedMemorySize, (int)sm3);

    prep_weffB<<<H, 256>>>(dw, psi);
    prep_hw1B<<<HW1B_F / 256, 256>>>(hw1);
    disco_head_mma<<<dim3(W / TW, H, B), TA, smD>>>(x, db, hb1, hw2, hb2, out);
    ffn_s1<<<dim3((unsigned)(M_PIX / 64), 4), 256, sm1>>>(out, fw1, fb1);
    ffn_s2<<<dim3((unsigned)(M_PIX / 64), 2), 256, sm2>>>(fw2, fb2);
    ffn_s3<<<dim3((unsigned)(M_PIX / 128)), 256, sm3>>>(fw3, fb3, out);
}

// round 6
// speedup vs baseline: 3.5663x; 1.2419x over previous
#include <cuda_runtime.h>

namespace {
constexpr int B = 2, H = 128, W = 256, MD = 34, LD = 32;
constexpr int NH = 4, SH = 64, K = 25, P = 7, R = 3;
constexpr int FF1 = 512, FF2 = 256;
constexpr int PP = P * P; // 49
constexpr long M_PIX = (long)B * H * W; // 65536

// ---------------- disco mma kernel config ----------------
constexpr int TW   = 32;
constexpr int PIX  = 8;
constexpr int NGRP = TW / PIX;
constexpr int TA   = 512;
constexpr int XCOLS = TW + 2 * R; // 38

constexpr int WEFFB_F = 8 * 7 * 32 * 2;      // 3584
constexpr int HW1B_F  = 4 * 4 * 8 * 32 * 2;  // 8192

constexpr int OFF_SX   = 0;
constexpr int OFF_SWB  = OFF_SX + LD * P * XCOLS;
constexpr int OFF_HW1B = OFF_SWB + WEFFB_F;
constexpr int OFF_SDA  = OFF_HW1B + HW1B_F;
constexpr int OFF_SDB  = OFF_SDA + 16 * 8 * 32 * 4;
constexpr int OFF_HB1  = OFF_SDB + SH;
constexpr int OFF_HW2  = OFF_HB1 + NH * 32;
constexpr int OFF_HB2  = OFF_HW2 + NH * 32;
constexpr int SMEM_D_F = OFF_HB2 + NH;

__device__ __forceinline__ float gelu_exact(float v) {
    return 0.5f * v * (1.0f + erff(v * 0.70710678118654752440f));
}

// NOTE: no cvt — raw fp32 bits fed to tf32 mma (HW truncates to 19 bits).
__device__ __forceinline__ void mma_tf32(float c[4], const float4& a, const float2& b) {
    const unsigned* A = reinterpret_cast<const unsigned*>(&a);
    const unsigned* Bv = reinterpret_cast<const unsigned*>(&b);
    asm volatile(
        "mma.sync.aligned.m16n8k8.row.col.f32.tf32.tf32.f32 "
        "{%0,%1,%2,%3},{%4,%5,%6,%7},{%8,%9},{%0,%1,%2,%3};\n"
        : "+f"(c[0]), "+f"(c[1]), "+f"(c[2]), "+f"(c[3])
        : "r"(A[0]), "r"(A[1]), "r"(A[2]), "r"(A[3]), "r"(Bv[0]), "r"(Bv[1]));
}
} // namespace

// device-global scratch (no runtime allocation)
// g_t1 holds stage-1 output in tiled A-frag layout:
//   float idx = ((rowtile*64 + kc*4 + ks)*32 + lane)*4 + rg
//   (rowtile = row/16, kc = k/32, ks = (k%32)/8)
__device__ float g_t1[M_PIX * FF1];        // 128 MB
__device__ float g_weffB[H * WEFFB_F];
__device__ float g_hw1B[HW1B_F];

// =====================================================================
// prep kernels: fold psi into disco_w per latitude; frag-layout weights
// =====================================================================
__global__ void prep_weffB(const float* __restrict__ dw,
                           const float* __restrict__ psi) {
    const int h = blockIdx.x;
    for (int e = threadIdx.x; e < WEFFB_F; e += blockDim.x) {
        int half = e & 1, t = e >> 1;
        int lane = t & 31; t >>= 5;
        int ks = t % 7, nt = t / 7;
        int g = lane >> 2, tg = lane & 3;
        int p = ks * 8 + tg + 4 * half;
        int s = nt * 8 + g;
        float acc = 0.f;
        if (p < PP) {
            #pragma unroll
            for (int k = 0; k < K; k++)
                acc += dw[s * K + k] * psi[(k * H + h) * PP + p];
        }
        g_weffB[h * WEFFB_F + e] = acc;
    }
}

__global__ void prep_hw1B(const float* __restrict__ hw1) {
    int e = blockIdx.x * blockDim.x + threadIdx.x;
    if (e >= HW1B_F) return;
    int half = e & 1, t = e >> 1;
    int lane = t & 31; t >>= 5;
    int ks = t & 7; t >>= 3;
    int nt = t & 3; int n = t >> 2;
    int g = lane >> 2, tg = lane & 3;
    int s = ks * 8 + tg + 4 * half;
    int o = nt * 8 + g;
    g_hw1B[e] = hw1[(n * SH + s) * 32 + o];
}

// =====================================================================
// disco conv + head MLP + residual (tf32 mma, warp-private intermediate)
// =====================================================================
__global__ __launch_bounds__(TA) void disco_head_mma(
    const float* __restrict__ x,   const float* __restrict__ db,
    const float* __restrict__ hb1, const float* __restrict__ hw2,
    const float* __restrict__ hb2, float* __restrict__ out)
{
    extern __shared__ float sm[];
    float* sx    = sm + OFF_SX;
    float* swB   = sm + OFF_SWB;
    float* shw1b = sm + OFF_HW1B;
    float* sdb   = sm + OFF_SDB;
    float* shb1  = sm + OFF_HB1;
    float* shw2  = sm + OFF_HW2;
    float* shb2  = sm + OFF_HB2;

    const int tid = threadIdx.x;
    const int lane = tid & 31, mt = tid >> 5;
    const int g  = lane >> 2, tg = lane & 3;
    const int w0 = blockIdx.x * TW;
    const int h  = blockIdx.y;
    const int b  = blockIdx.z;

    for (int e = tid; e < WEFFB_F; e += TA) swB[e] = g_weffB[h * WEFFB_F + e];
    for (int e = tid; e < HW1B_F; e += TA)  shw1b[e] = g_hw1B[e];
    if (tid < SH) sdb[tid] = db[tid];
    if (tid < NH * 32) { shb1[tid] = hb1[tid]; shw2[tid] = hw2[tid]; }
    if (tid < NH) shb2[tid] = hb2[tid];

    for (int i = tid; i < LD * P * XCOLS; i += TA) {
        int ld = i & 31; int pos = i >> 5;
        int r = pos / XCOLS, c = pos % XCOLS;
        int lat = h + r - R; lat = lat < 0 ? 0 : (lat > H - 1 ? H - 1 : lat);
        int lon = (w0 + c - R + W) & (W - 1);
        sx[(ld * P + r) * XCOLS + c] = x[((b * H + lat) * W + lon) * MD + ld];
    }
    for (int i = tid; i < TW * 2; i += TA) {
        int px = i >> 1, j = i & 1;
        int gi = ((b * H + h) * W + (w0 + px)) * MD + LD + j;
        out[gi] = x[gi];
    }
    __syncthreads();

    const int nh  = mt >> 2;
    const int ld0 = nh * 8 + (mt & 3) * 2;
    const int ld1 = ld0 + 1;
    const int px  = g;
    const int base0 = ld0 * P * XCOLS;
    const int base1 = ld1 * P * XCOLS;
    float* sdAw = sm + OFF_SDA + mt * (8 * 32 * 4);

    // hoist p/7, p%7 out of the group loop
    int roff0[7], roff1[7]; bool ok0[7], ok1[7];
    #pragma unroll
    for (int ks = 0; ks < 7; ks++) {
        int p0 = ks * 8 + tg, p1 = p0 + 4;
        ok0[ks] = p0 < PP; ok1[ks] = p1 < PP;
        roff0[ks] = ok0[ks] ? (p0 / 7) * XCOLS + (p0 % 7) : 0;
        roff1[ks] = ok1[ks] ? (p1 / 7) * XCOLS + (p1 % 7) : 0;
    }

    const float2* swB2  = reinterpret_cast<const float2*>(swB);
    const float2* hw1b2 = reinterpret_cast<const float2*>(shw1b);
    const float4* sdA4  = reinterpret_cast<const float4*>(sm + OFF_SDA);

    for (int grp = 0; grp < NGRP; grp++) {
        const int cbase = grp * PIX + px;
        const int cb0 = base0 + cbase, cb1 = base1 + cbase;

        // phase 1: d = taps @ weff  (M=16/warp, N=64, K=56)
        float c1[8][4] = {};
        #pragma unroll
        for (int ks = 0; ks < 7; ks++) {
            float4 a;
            a.x = ok0[ks] ? sx[cb0 + roff0[ks]] : 0.f;
            a.y = ok0[ks] ? sx[cb1 + roff0[ks]] : 0.f;
            a.z = ok1[ks] ? sx[cb0 + roff1[ks]] : 0.f;
            a.w = ok1[ks] ? sx[cb1 + roff1[ks]] : 0.f;
            #pragma unroll
            for (int nt = 0; nt < 8; nt++) {
                float2 bb = swB2[(nt * 7 + ks) * 32 + lane];
                mma_tf32(c1[nt], a, bb);
            }
        }

        // epilogue 1: +bias, scatter to warp-private A-frag layout
        #pragma unroll
        for (int nt = 0; nt < 8; nt++) {
            const int kk0 = 2 * tg, kk1 = kk0 + 1;
            const float b0 = sdb[nt * 8 + kk0], b1 = sdb[nt * 8 + kk1];
            const int i0 = (nt * 32 + g * 4 + (kk0 & 3)) * 4 + ((kk0 >> 2) << 1);
            const int i1 = (nt * 32 + g * 4 + (kk1 & 3)) * 4 + ((kk1 >> 2) << 1);
            sdAw[i0]     = c1[nt][0] + b0;
            sdAw[i1]     = c1[nt][1] + b1;
            sdAw[i0 + 1] = c1[nt][2] + b0;
            sdAw[i1 + 1] = c1[nt][3] + b1;
        }
        __syncwarp();

        // phase 2: h = d @ hw1[head]  (M=16, N=32, K=64)
        float c2[4][4] = {};
        #pragma unroll
        for (int ks = 0; ks < 8; ks++) {
            float4 a = sdA4[(mt * 8 + ks) * 32 + lane];
            #pragma unroll
            for (int nt2 = 0; nt2 < 4; nt2++) {
                float2 bb = hw1b2[((nh * 4 + nt2) * 8 + ks) * 32 + lane];
                mma_tf32(c2[nt2], a, bb);
            }
        }

        // epilogue 2: gelu + hw2 dot + lane reduce + residual
        float part0 = 0.f, part1 = 0.f;
        #pragma unroll
        for (int nt2 = 0; nt2 < 4; nt2++) {
            const int o0 = nt2 * 8 + 2 * tg, o1 = o0 + 1;
            const float w0v = shw2[nh * 32 + o0], w1v = shw2[nh * 32 + o1];
            const float bb0 = shb1[nh * 32 + o0], bb1 = shb1[nh * 32 + o1];
            part0 += gelu_exact(c2[nt2][0] + bb0) * w0v
                   + gelu_exact(c2[nt2][1] + bb1) * w1v;
            part1 += gelu_exact(c2[nt2][2] + bb0) * w0v
                   + gelu_exact(c2[nt2][3] + bb1) * w1v;
        }
        part0 += __shfl_xor_sync(0xffffffffu, part0, 1);
        part0 += __shfl_xor_sync(0xffffffffu, part0, 2);
        part1 += __shfl_xor_sync(0xffffffffu, part1, 1);
        part1 += __shfl_xor_sync(0xffffffffu, part1, 2);
        if (tg == 0) {
            const float v0 = part0 + shb2[nh] + sx[cb0 + R * XCOLS + R];
            const float v1 = part1 + shb2[nh] + sx[cb1 + R * XCOLS + R];
            const long o = ((long)(b * H + h) * W + w0 + grp * PIX + px) * MD;
            out[o + ld0] = v0;
            out[o + ld1] = v1;
        }
        __syncwarp();
    }
}

// =====================================================================
// FFN stage 1: g_t1(frag) = gelu(out[:,:34] @ fw1 + fb1)
// MT=64, NT=256 (grid.y=2), 512 thr, 16 warps = 4mw x 4nw (8 n8/warp)
// =====================================================================
namespace {
constexpr int S1_AF = 4 * 5 * 32 * 4;   // 2560
constexpr int S1_BF = 32 * 5 * 32 * 2;  // 10240
}
__global__ __launch_bounds__(512) void ffn_s1(
    const float* __restrict__ xin, const float* __restrict__ fw1,
    const float* __restrict__ fb1)
{
    extern __shared__ float sm[];
    float* sA = sm;
    float* sB = sm + S1_AF;
    const int tid = threadIdx.x, lane = tid & 31, w = tid >> 5;
    const int mw = w >> 2, nw = w & 3;
    const long r0 = (long)blockIdx.x * 64;
    const int  n0 = blockIdx.y * 256;

    // A: 64 rows x 40 k (pad 34->40), 5 elems/thread, frag layout
    {
        const int r = tid >> 3, rr7 = r & 7, rhi = (r >> 3) & 1, mt = r >> 4;
        const int kb = (tid & 7) * 5;
        #pragma unroll
        for (int j = 0; j < 5; j++) {
            const int k = kb + j;
            const float v = (k < MD) ? xin[(r0 + r) * MD + k] : 0.f;
            sA[((mt * 5 + (k >> 3)) * 32 + rr7 * 4 + (k & 3)) * 4
               + rhi + (((k >> 2) & 1) << 1)] = v;
        }
    }
    // B: 40 x 256, col per thread (shifts only), frag layout
    {
        const int n = tid & 255, kb = tid >> 8;
        const int nt = n >> 3, gg = n & 7;
        #pragma unroll
        for (int i = 0; i < 20; i++) {
            const int k = kb + 2 * i;
            const float v = (k < MD) ? fw1[k * FF1 + n0 + n] : 0.f;
            sB[((nt * 5 + (k >> 3)) * 32 + gg * 4 + (k & 3)) * 2 + ((k >> 2) & 1)] = v;
        }
    }
    __syncthreads();

    float c[8][4] = {};
    #pragma unroll
    for (int ks = 0; ks < 5; ks++) {
        float4 a = reinterpret_cast<const float4*>(sA)[(mw * 5 + ks) * 32 + lane];
        #pragma unroll
        for (int ni = 0; ni < 8; ni++) {
            float2 bb = reinterpret_cast<const float2*>(sB)[((nw * 8 + ni) * 5 + ks) * 32 + lane];
            mma_tf32(c[ni], a, bb);
        }
    }

    // epilogue: gelu, store to g_t1 in A-frag layout
    // FIX (R5 bug): row-tile stride is 64 k8-steps (16 kc * 4 ks), was 16.
    const int g = lane >> 2, tg = lane & 3;
    const long rt = blockIdx.x * 4 + mw;
    #pragma unroll
    for (int ni = 0; ni < 8; ni++) {
        const int n = n0 + (nw * 8 + ni) * 8 + 2 * tg;
        const int kc = n >> 5, ks2 = (n >> 3) & 3;
        const int kk0 = n & 7, kk1 = kk0 + 1;
        const long base = (rt * 64 + kc * 4 + ks2) * 32;
        const int rgA = ((kk0 >> 2) & 1) << 1;
        const long i0 = (base + g * 4 + (kk0 & 3)) * 4 + rgA;
        const long i1 = (base + g * 4 + (kk1 & 3)) * 4 + rgA;
        const float b0 = fb1[n], b1 = fb1[n + 1];
        g_t1[i0]     = gelu_exact(c[ni][0] + b0);
        g_t1[i1]     = gelu_exact(c[ni][1] + b1);
        g_t1[i0 + 1] = gelu_exact(c[ni][2] + b0);
        g_t1[i1 + 1] = gelu_exact(c[ni][3] + b1);
    }
}

// =====================================================================
// FFN stages 2+3 fused: t2 = gelu(t1 @ fw2 + fb2) kept in smem frags;
// out[:, :32] += t2 @ fw3 + fb3.   MT=64, NT=256, 512 thr.
// =====================================================================
namespace {
constexpr int SF3_F  = 4 * 32 * 32 * 2;  // 8192 (fw3 B-frags)
constexpr int S2_AF  = 4 * 4 * 32 * 4;   // 2048
constexpr int S2_BF  = 32 * 4 * 32 * 2;  // 8192
constexpr int S2_BUF = S2_AF + S2_BF;    // 10240 per buffer
constexpr int S23_F  = SF3_F + 2 * S2_BUF; // 28672 floats = 112 KB
}
__global__ __launch_bounds__(512) void ffn_s2s3(
    const float* __restrict__ fw2, const float* __restrict__ fb2,
    const float* __restrict__ fw3, const float* __restrict__ fb3,
    float* __restrict__ out)
{
    extern __shared__ float sm[];
    float* sf3  = sm;
    float* bufs = sm + SF3_F;
    const int tid = threadIdx.x, lane = tid & 31, w = tid >> 5;
    const int mw = w >> 2, nw = w & 3;
    const long r0 = (long)blockIdx.x * 64;
    const long rt0 = (long)blockIdx.x * 4;

    // stage fw3 into B-frag layout (used after mainloop)
    {
        const int n3 = tid & 31, kb3 = tid >> 5;
        const int nt = n3 >> 3, gg = n3 & 7;
        #pragma unroll
        for (int i = 0; i < 16; i++) {
            const int k = kb3 + 16 * i;
            sf3[((nt * 32 + (k >> 3)) * 32 + gg * 4 + (k & 3)) * 2 + ((k >> 2) & 1)]
                = fw3[k * LD + n3];
        }
    }

    float c[8][4] = {};
    const int nB = tid & 255, kbB = tid >> 8;
    const int ntB = nB >> 3, ggB = nB & 7;

    for (int kc = 0; kc < 16; kc++) {
        float* sA = bufs + (kc & 1) * S2_BUF;
        float* sB = sA + S2_AF;
        // A: pure coalesced float4 copy from frag-layout g_t1
        // FIX (R5 bug): per-rowtile stride is 2048 float4 (16 rows x 512 k), was 512.
        reinterpret_cast<float4*>(sA)[tid] =
            reinterpret_cast<const float4*>(g_t1)
                [(rt0 + (tid >> 7)) * 2048 + kc * 128 + (tid & 127)];
        // B: fw2 chunk 32x256, shifts-only frag staging
        {
            const int k0 = kc * 32;
            #pragma unroll
            for (int i = 0; i < 16; i++) {
                const int k = kbB + 2 * i;
                sB[((ntB * 4 + (k >> 3)) * 32 + ggB * 4 + (k & 3)) * 2 + ((k >> 2) & 1)]
                    = fw2[(k0 + k) * FF2 + nB];
            }
        }
        __syncthreads();
        #pragma unroll
        for (int ks = 0; ks < 4; ks++) {
            float4 a = reinterpret_cast<const float4*>(sA)[(mw * 4 + ks) * 32 + lane];
            #pragma unroll
            for (int ni = 0; ni < 8; ni++) {
                float2 bb = reinterpret_cast<const float2*>(sB)[((nw * 8 + ni) * 4 + ks) * 32 + lane];
                mma_tf32(c[ni], a, bb);
            }
        }
    }
    __syncthreads();

    // write gelu(t2) into smem A-frag layout (overlays the dead buffers)
    float* sT2 = bufs; // 16384 floats needed, 20480 available
    const int g = lane >> 2, tg = lane & 3;
    #pragma unroll
    for (int ni = 0; ni < 8; ni++) {
        const int nt = nw * 8 + ni;           // == stage-3 ks index
        const int n2 = nt * 8 + 2 * tg;
        const int kk0 = n2 & 7, kk1 = kk0 + 1;
        const int base = (mw * 32 + nt) * 32;
        const int rgA = ((kk0 >> 2) & 1) << 1;
        const int i0 = (base + g * 4 + (kk0 & 3)) * 4 + rgA;
        const int i1 = (base + g * 4 + (kk1 & 3)) * 4 + rgA;
        const float b0 = fb2[n2], b1 = fb2[n2 + 1];
        sT2[i0]     = gelu_exact(c[ni][0] + b0);
        sT2[i1]     = gelu_exact(c[ni][1] + b1);
        sT2[i0 + 1] = gelu_exact(c[ni][2] + b0);
        sT2[i1 + 1] = gelu_exact(c[ni][3] + b1);
    }
    __syncthreads();

    // stage 3: [64,256] x [256,32], warp (mw,nw) -> m16 tile mw, n8 tile nw
    float c3[4] = {};
    #pragma unroll
    for (int ks = 0; ks < 32; ks++) {
        float4 a = reinterpret_cast<const float4*>(sT2)[(mw * 32 + ks) * 32 + lane];
        float2 bb = reinterpret_cast<const float2*>(sf3)[(nw * 32 + ks) * 32 + lane];
        mma_tf32(c3, a, bb);
    }

    const int col = nw * 8 + 2 * tg;
    const long rlo = r0 + mw * 16 + g, rhi = rlo + 8;
    const float b0 = fb3[col], b1 = fb3[col + 1];
    out[rlo * MD + col]     += c3[0] + b0;
    out[rlo * MD + col + 1] += c3[1] + b1;
    out[rhi * MD + col]     += c3[2] + b0;
    out[rhi * MD + col + 1] += c3[3] + b1;
}

extern "C" void kernel_launch(void* const* d_in, const int* in_sizes, int n_in,
                              void* d_out, int out_size) {
    const float* x   = (const float*)d_in[0];
    const float* psi = (const float*)d_in[1];
    const float* dw  = (const float*)d_in[2];
    const float* db  = (const float*)d_in[3];
    const float* hw1 = (const float*)d_in[4];
    const float* hb1 = (const float*)d_in[5];
    const float* hw2 = (const float*)d_in[6];
    const float* hb2 = (const float*)d_in[7];
    const float* fw1 = (const float*)d_in[8];
    const float* fb1 = (const float*)d_in[9];
    const float* fw2 = (const float*)d_in[10];
    const float* fb2 = (const float*)d_in[11];
    const float* fw3 = (const float*)d_in[12];
    const float* fb3 = (const float*)d_in[13];
    float* out = (float*)d_out;

    const size_t smD  = SMEM_D_F * sizeof(float);
    const size_t sm1  = (S1_AF + S1_BF) * sizeof(float);
    const size_t sm23 = S23_F * sizeof(float);
    cudaFuncSetAttribute(disco_head_mma, cudaFuncAttributeMaxDynamicSharedMemorySize, (int)smD);
    cudaFuncSetAttribute(ffn_s1, cudaFuncAttributeMaxDynamicSharedMemorySize, (int)sm1);
    cudaFuncSetAttribute(ffn_s2s3, cudaFuncAttributeMaxDynamicSharedMemorySize, (int)sm23);

    prep_weffB<<<H, 256>>>(dw, psi);
    prep_hw1B<<<HW1B_F / 256, 256>>>(hw1);
    disco_head_mma<<<dim3(W / TW, H, B), TA, smD>>>(x, db, hb1, hw2, hb2, out);
    ffn_s1<<<dim3((unsigned)(M_PIX / 64), 2), 512, sm1>>>(out, fw1, fb1);
    ffn_s2s3<<<(unsigned)(M_PIX / 64), 512, sm23>>>(fw2, fb2, fw3, fb3, out);
}

// round 7
// speedup vs baseline: 3.9664x; 1.1122x over previous
#include <cuda_runtime.h>

namespace {
constexpr int B = 2, H = 128, W = 256, MD = 34, LD = 32;
constexpr int NH = 4, SH = 64, K = 25, P = 7, R = 3;
constexpr int FF1 = 512, FF2 = 256;
constexpr int PP = P * P; // 49
constexpr long M_PIX = (long)B * H * W; // 65536

// ---------------- disco mma kernel config ----------------
constexpr int TW   = 32;
constexpr int PIX  = 8;
constexpr int NGRP = TW / PIX;
constexpr int TA   = 512;
constexpr int XCOLS = TW + 2 * R; // 38

constexpr int WEFFB_F = 8 * 7 * 32 * 2;      // 3584
constexpr int HW1B_F  = 4 * 4 * 8 * 32 * 2;  // 8192
constexpr int FW1B_F  = 64 * 5 * 32 * 2;     // 20480 (k padded 34->40)
constexpr int FW2B_F  = 16 * 32 * 4 * 32 * 2;// 131072
constexpr int FW3B_F  = 4 * 32 * 32 * 2;     // 8192

constexpr int OFF_SX   = 0;
constexpr int OFF_SWB  = OFF_SX + LD * P * XCOLS;
constexpr int OFF_HW1B = OFF_SWB + WEFFB_F;
constexpr int OFF_SDA  = OFF_HW1B + HW1B_F;
constexpr int OFF_SDB  = OFF_SDA + 16 * 8 * 32 * 4;
constexpr int OFF_HB1  = OFF_SDB + SH;
constexpr int OFF_HW2  = OFF_HB1 + NH * 32;
constexpr int OFF_HB2  = OFF_HW2 + NH * 32;
constexpr int SMEM_D_F = OFF_HB2 + NH;

__device__ __forceinline__ float gelu_exact(float v) {
    return 0.5f * v * (1.0f + erff(v * 0.70710678118654752440f));
}

__device__ __forceinline__ float f2tf_f(float f) {
    unsigned u;
    asm("cvt.rna.tf32.f32 %0, %1;" : "=r"(u) : "f"(f));
    return __uint_as_float(u);
}

__device__ __forceinline__ void mma_tf32(float c[4], const float4& a, const float2& b) {
    const unsigned* A = reinterpret_cast<const unsigned*>(&a);
    const unsigned* Bv = reinterpret_cast<const unsigned*>(&b);
    asm volatile(
        "mma.sync.aligned.m16n8k8.row.col.f32.tf32.tf32.f32 "
        "{%0,%1,%2,%3},{%4,%5,%6,%7},{%8,%9},{%0,%1,%2,%3};\n"
        : "+f"(c[0]), "+f"(c[1]), "+f"(c[2]), "+f"(c[3])
        : "r"(A[0]), "r"(A[1]), "r"(A[2]), "r"(A[3]), "r"(Bv[0]), "r"(Bv[1]));
}
} // namespace

// device-global scratch (no runtime allocation)
// g_t1: stage-1 output in tiled A-frag layout:
//   float idx = ((rowtile*64 + kc*4 + ks)*32 + lane)*4 + rg
__device__ __align__(16) float g_t1[M_PIX * FF1];   // 128 MB
__device__ __align__(16) float g_weffB[H * WEFFB_F];
__device__ __align__(16) float g_hw1B[HW1B_F];
__device__ __align__(16) float g_fw1B[FW1B_F];
__device__ __align__(16) float g_fw2B[FW2B_F];
__device__ __align__(16) float g_fw3B[FW3B_F];

// =====================================================================
// prep: fold psi into disco_w per latitude (B-frag layout, rounded)
// =====================================================================
__global__ void prep_weffB(const float* __restrict__ dw,
                           const float* __restrict__ psi) {
    const int h = blockIdx.x;
    for (int e = threadIdx.x; e < WEFFB_F; e += blockDim.x) {
        int half = e & 1, t = e >> 1;
        int lane = t & 31; t >>= 5;
        int ks = t % 7, nt = t / 7;
        int g = lane >> 2, tg = lane & 3;
        int p = ks * 8 + tg + 4 * half;
        int s = nt * 8 + g;
        float acc = 0.f;
        if (p < PP) {
            #pragma unroll
            for (int k = 0; k < K; k++)
                acc += dw[s * K + k] * psi[(k * H + h) * PP + p];
        }
        g_weffB[h * WEFFB_F + e] = f2tf_f(acc);
    }
}

// =====================================================================
// prep: hw1 / fw1 / fw3 into B-frag layouts, rounded (merged kernel)
// =====================================================================
__global__ void prep_small(const float* __restrict__ hw1,
                           const float* __restrict__ fw1,
                           const float* __restrict__ fw3) {
    int e = blockIdx.x * blockDim.x + threadIdx.x;
    if (e < HW1B_F) {
        int half = e & 1, t = e >> 1;
        int lane = t & 31; t >>= 5;
        int ks = t & 7; t >>= 3;
        int nt = t & 3; int n = t >> 2;
        int g = lane >> 2, tg = lane & 3;
        int s = ks * 8 + tg + 4 * half;
        int o = nt * 8 + g;
        g_hw1B[e] = f2tf_f(hw1[(n * SH + s) * 32 + o]);
        return;
    }
    e -= HW1B_F;
    if (e < FW1B_F) {
        int half = e & 1, t = e >> 1;
        int lane = t & 31; t >>= 5;
        int ks = t % 5, nt = t / 5;
        int g = lane >> 2, tg = lane & 3;
        int k = ks * 8 + tg + 4 * half;
        int n = nt * 8 + g;
        g_fw1B[e] = (k < MD) ? f2tf_f(fw1[k * FF1 + n]) : 0.f;
        return;
    }
    e -= FW1B_F;
    if (e < FW3B_F) {
        int half = e & 1, t = e >> 1;
        int lane = t & 31; t >>= 5;
        int ks = t & 31, nt = t >> 5;
        int g = lane >> 2, tg = lane & 3;
        int k = ks * 8 + tg + 4 * half;
        int n = nt * 8 + g;
        g_fw3B[e] = f2tf_f(fw3[k * LD + n]);
    }
}

// =====================================================================
// prep: fw2 into per-chunk B-frag layout, rounded
//   g_fw2B[kc*8192 + ((nt*4+ks)*32+lane)*2+half]
// =====================================================================
__global__ void prep_fw2B(const float* __restrict__ fw2) {
    int e = blockIdx.x * blockDim.x + threadIdx.x;
    if (e >= FW2B_F) return;
    int kc = e >> 13, r = e & 8191;
    int half = r & 1; r >>= 1;
    int lane = r & 31; r >>= 5;
    int ks = r & 3; int nt = r >> 2;
    int g = lane >> 2, tg = lane & 3;
    int k = kc * 32 + ks * 8 + tg + 4 * half;
    int n = nt * 8 + g;
    g_fw2B[e] = f2tf_f(fw2[k * FF2 + n]);
}

// =====================================================================
// disco conv + head MLP + residual (tf32 mma, warp-private intermediate)
// =====================================================================
__global__ __launch_bounds__(TA) void disco_head_mma(
    const float* __restrict__ x,   const float* __restrict__ db,
    const float* __restrict__ hb1, const float* __restrict__ hw2,
    const float* __restrict__ hb2, float* __restrict__ out)
{
    extern __shared__ float sm[];
    float* sx    = sm + OFF_SX;
    float* swB   = sm + OFF_SWB;
    float* shw1b = sm + OFF_HW1B;
    float* sdb   = sm + OFF_SDB;
    float* shb1  = sm + OFF_HB1;
    float* shw2  = sm + OFF_HW2;
    float* shb2  = sm + OFF_HB2;

    const int tid = threadIdx.x;
    const int lane = tid & 31, mt = tid >> 5;
    const int g  = lane >> 2, tg = lane & 3;
    const int w0 = blockIdx.x * TW;
    const int h  = blockIdx.y;
    const int b  = blockIdx.z;

    for (int e = tid; e < WEFFB_F; e += TA) swB[e] = g_weffB[h * WEFFB_F + e];
    for (int e = tid; e < HW1B_F; e += TA)  shw1b[e] = g_hw1B[e];
    if (tid < SH) sdb[tid] = db[tid];
    if (tid < NH * 32) { shb1[tid] = hb1[tid]; shw2[tid] = hw2[tid]; }
    if (tid < NH) shb2[tid] = hb2[tid];

    for (int i = tid; i < LD * P * XCOLS; i += TA) {
        int ld = i & 31; int pos = i >> 5;
        int r = pos / XCOLS, c = pos % XCOLS;
        int lat = h + r - R; lat = lat < 0 ? 0 : (lat > H - 1 ? H - 1 : lat);
        int lon = (w0 + c - R + W) & (W - 1);
        sx[(ld * P + r) * XCOLS + c] = x[((b * H + lat) * W + lon) * MD + ld];
    }
    for (int i = tid; i < TW * 2; i += TA) {
        int px = i >> 1, j = i & 1;
        int gi = ((b * H + h) * W + (w0 + px)) * MD + LD + j;
        out[gi] = x[gi];
    }
    __syncthreads();

    const int nh  = mt >> 2;
    const int ld0 = nh * 8 + (mt & 3) * 2;
    const int ld1 = ld0 + 1;
    const int px  = g;
    const int base0 = ld0 * P * XCOLS;
    const int base1 = ld1 * P * XCOLS;
    float* sdAw = sm + OFF_SDA + mt * (8 * 32 * 4);

    int roff0[7], roff1[7]; bool ok0[7], ok1[7];
    #pragma unroll
    for (int ks = 0; ks < 7; ks++) {
        int p0 = ks * 8 + tg, p1 = p0 + 4;
        ok0[ks] = p0 < PP; ok1[ks] = p1 < PP;
        roff0[ks] = ok0[ks] ? (p0 / 7) * XCOLS + (p0 % 7) : 0;
        roff1[ks] = ok1[ks] ? (p1 / 7) * XCOLS + (p1 % 7) : 0;
    }

    const float2* swB2  = reinterpret_cast<const float2*>(swB);
    const float2* hw1b2 = reinterpret_cast<const float2*>(shw1b);
    const float4* sdA4  = reinterpret_cast<const float4*>(sm + OFF_SDA);
    float2* sdAw2 = reinterpret_cast<float2*>(sdAw);

    for (int grp = 0; grp < NGRP; grp++) {
        const int cbase = grp * PIX + px;
        const int cb0 = base0 + cbase, cb1 = base1 + cbase;

        // phase 1: d = taps @ weff  (M=16/warp, N=64, K=56)
        float c1[8][4] = {};
        #pragma unroll
        for (int ks = 0; ks < 7; ks++) {
            float4 a;
            a.x = f2tf_f(ok0[ks] ? sx[cb0 + roff0[ks]] : 0.f);
            a.y = f2tf_f(ok0[ks] ? sx[cb1 + roff0[ks]] : 0.f);
            a.z = f2tf_f(ok1[ks] ? sx[cb0 + roff1[ks]] : 0.f);
            a.w = f2tf_f(ok1[ks] ? sx[cb1 + roff1[ks]] : 0.f);
            #pragma unroll
            for (int nt = 0; nt < 8; nt++) {
                float2 bb = swB2[(nt * 7 + ks) * 32 + lane];
                mma_tf32(c1[nt], a, bb);
            }
        }

        // epilogue 1: +bias, round, float2 scatter into A-frag layout
        #pragma unroll
        for (int nt = 0; nt < 8; nt++) {
            const int kk0 = 2 * tg, kk1 = kk0 + 1;
            const float b0 = sdb[nt * 8 + kk0], b1 = sdb[nt * 8 + kk1];
            const int i0 = (nt * 32 + g * 4 + (kk0 & 3)) * 4 + ((kk0 >> 2) << 1);
            const int i1 = (nt * 32 + g * 4 + (kk1 & 3)) * 4 + ((kk1 >> 2) << 1);
            sdAw2[i0 >> 1] = make_float2(f2tf_f(c1[nt][0] + b0), f2tf_f(c1[nt][2] + b0));
            sdAw2[i1 >> 1] = make_float2(f2tf_f(c1[nt][1] + b1), f2tf_f(c1[nt][3] + b1));
        }
        __syncwarp();

        // phase 2: h = d @ hw1[head]  (M=16, N=32, K=64)
        float c2[4][4] = {};
        #pragma unroll
        for (int ks = 0; ks < 8; ks++) {
            float4 a = sdA4[(mt * 8 + ks) * 32 + lane];
            #pragma unroll
            for (int nt2 = 0; nt2 < 4; nt2++) {
                float2 bb = hw1b2[((nh * 4 + nt2) * 8 + ks) * 32 + lane];
                mma_tf32(c2[nt2], a, bb);
            }
        }

        // epilogue 2: gelu + hw2 dot + lane reduce + residual (fp32 path)
        float part0 = 0.f, part1 = 0.f;
        #pragma unroll
        for (int nt2 = 0; nt2 < 4; nt2++) {
            const int o0 = nt2 * 8 + 2 * tg, o1 = o0 + 1;
            const float w0v = shw2[nh * 32 + o0], w1v = shw2[nh * 32 + o1];
            const float bb0 = shb1[nh * 32 + o0], bb1 = shb1[nh * 32 + o1];
            part0 += gelu_exact(c2[nt2][0] + bb0) * w0v
                   + gelu_exact(c2[nt2][1] + bb1) * w1v;
            part1 += gelu_exact(c2[nt2][2] + bb0) * w0v
                   + gelu_exact(c2[nt2][3] + bb1) * w1v;
        }
        part0 += __shfl_xor_sync(0xffffffffu, part0, 1);
        part0 += __shfl_xor_sync(0xffffffffu, part0, 2);
        part1 += __shfl_xor_sync(0xffffffffu, part1, 1);
        part1 += __shfl_xor_sync(0xffffffffu, part1, 2);
        if (tg == 0) {
            const float v0 = part0 + shb2[nh] + sx[cb0 + R * XCOLS + R];
            const float v1 = part1 + shb2[nh] + sx[cb1 + R * XCOLS + R];
            const long o = ((long)(b * H + h) * W + w0 + grp * PIX + px) * MD;
            out[o + ld0] = v0;
            out[o + ld1] = v1;
        }
        __syncwarp();
    }
}

// =====================================================================
// FFN stage 1: g_t1(frag) = gelu(out[:,:34] @ fw1 + fb1)
// MT=64, NT=256 (grid.y=2), 512 thr, 16 warps = 4mw x 4nw
// =====================================================================
namespace {
constexpr int S1_AF = 4 * 5 * 32 * 4;   // 2560
constexpr int S1_BF = 32 * 5 * 32 * 2;  // 10240
}
__global__ __launch_bounds__(512) void ffn_s1(
    const float* __restrict__ xin, const float* __restrict__ fb1)
{
    extern __shared__ float sm[];
    float* sA = sm;
    float* sB = sm + S1_AF;
    const int tid = threadIdx.x, lane = tid & 31, w = tid >> 5;
    const int mw = w >> 2, nw = w & 3;
    const long r0 = (long)blockIdx.x * 64;
    const int  n0 = blockIdx.y * 256;

    // A: 64 rows x 40 k (pad), rounded, frag layout
    {
        const int r = tid >> 3, rr7 = r & 7, rhi = (r >> 3) & 1, mt = r >> 4;
        const int kb = (tid & 7) * 5;
        #pragma unroll
        for (int j = 0; j < 5; j++) {
            const int k = kb + j;
            const float v = (k < MD) ? f2tf_f(xin[(r0 + r) * MD + k]) : 0.f;
            sA[((mt * 5 + (k >> 3)) * 32 + rr7 * 4 + (k & 3)) * 4
               + rhi + (((k >> 2) & 1) << 1)] = v;
        }
    }
    // B: coalesced float4 copy from pre-swizzled g_fw1B
    {
        const float4* src = reinterpret_cast<const float4*>(g_fw1B + blockIdx.y * S1_BF);
        float4* dst = reinterpret_cast<float4*>(sB);
        #pragma unroll
        for (int i = 0; i < 5; i++) dst[tid + i * 512] = src[tid + i * 512];
    }
    __syncthreads();

    float c[8][4] = {};
    #pragma unroll
    for (int ks = 0; ks < 5; ks++) {
        float4 a = reinterpret_cast<const float4*>(sA)[(mw * 5 + ks) * 32 + lane];
        #pragma unroll
        for (int ni = 0; ni < 8; ni++) {
            float2 bb = reinterpret_cast<const float2*>(sB)[((nw * 8 + ni) * 5 + ks) * 32 + lane];
            mma_tf32(c[ni], a, bb);
        }
    }

    // epilogue: gelu, round, float2 stores to g_t1 (A-frag layout)
    const int g = lane >> 2, tg = lane & 3;
    const long rt = blockIdx.x * 4 + mw;
    float2* t1v2 = reinterpret_cast<float2*>(g_t1);
    #pragma unroll
    for (int ni = 0; ni < 8; ni++) {
        const int n = n0 + (nw * 8 + ni) * 8 + 2 * tg;
        const int kc = n >> 5, ks2 = (n >> 3) & 3;
        const int kk0 = n & 7, kk1 = kk0 + 1;
        const long base = (rt * 64 + kc * 4 + ks2) * 32;
        const int rgA = ((kk0 >> 2) & 1) << 1;
        const long i0 = (base + g * 4 + (kk0 & 3)) * 4 + rgA;
        const long i1 = (base + g * 4 + (kk1 & 3)) * 4 + rgA;
        const float b0 = fb1[n], b1 = fb1[n + 1];
        t1v2[i0 >> 1] = make_float2(f2tf_f(gelu_exact(c[ni][0] + b0)),
                                    f2tf_f(gelu_exact(c[ni][2] + b0)));
        t1v2[i1 >> 1] = make_float2(f2tf_f(gelu_exact(c[ni][1] + b1)),
                                    f2tf_f(gelu_exact(c[ni][3] + b1)));
    }
}

// =====================================================================
// FFN stages 2+3 fused: t2 = gelu(t1 @ fw2 + fb2) in smem frags;
// out[:, :32] += t2 @ fw3 + fb3.   MT=64, NT=256, 512 thr.
// =====================================================================
namespace {
constexpr int SF3_F  = 4 * 32 * 32 * 2;    // 8192 (fw3 B-frags)
constexpr int S2_AF  = 4 * 4 * 32 * 4;     // 2048
constexpr int S2_BF  = 32 * 4 * 32 * 2;    // 8192
constexpr int S2_BUF = S2_AF + S2_BF;      // 10240 per buffer
constexpr int S23_F  = SF3_F + 2 * S2_BUF; // 28672 floats = 112 KB
}
__global__ __launch_bounds__(512) void ffn_s2s3(
    const float* __restrict__ fb2, const float* __restrict__ fb3,
    float* __restrict__ out)
{
    extern __shared__ float sm[];
    float* sf3  = sm;
    float* bufs = sm + SF3_F;
    const int tid = threadIdx.x, lane = tid & 31, w = tid >> 5;
    const int mw = w >> 2, nw = w & 3;
    const long r0 = (long)blockIdx.x * 64;
    const long rt0 = (long)blockIdx.x * 4;

    // stage fw3 B-frags: coalesced copy
    {
        const float4* src = reinterpret_cast<const float4*>(g_fw3B);
        float4* dst = reinterpret_cast<float4*>(sf3);
        #pragma unroll
        for (int i = 0; i < 4; i++) dst[tid + i * 512] = src[tid + i * 512];
    }

    float c[8][4] = {};
    const float4* t1v4 = reinterpret_cast<const float4*>(g_t1);
    const float4* fw2v4 = reinterpret_cast<const float4*>(g_fw2B);

    for (int kc = 0; kc < 16; kc++) {
        float* sA = bufs + (kc & 1) * S2_BUF;
        float* sB = sA + S2_AF;
        // A: coalesced float4 copy from frag-layout g_t1
        reinterpret_cast<float4*>(sA)[tid] =
            t1v4[(rt0 + (tid >> 7)) * 2048 + kc * 128 + (tid & 127)];
        // B: coalesced float4 copy from pre-swizzled g_fw2B chunk
        {
            float4* dst = reinterpret_cast<float4*>(sB);
            #pragma unroll
            for (int i = 0; i < 4; i++)
                dst[tid + i * 512] = fw2v4[kc * 2048 + tid + i * 512];
        }
        __syncthreads();
        #pragma unroll
        for (int ks = 0; ks < 4; ks++) {
            float4 a = reinterpret_cast<const float4*>(sA)[(mw * 4 + ks) * 32 + lane];
            #pragma unroll
            for (int ni = 0; ni < 8; ni++) {
                float2 bb = reinterpret_cast<const float2*>(sB)[((nw * 8 + ni) * 4 + ks) * 32 + lane];
                mma_tf32(c[ni], a, bb);
            }
        }
        __syncthreads();
    }

    // write gelu(t2) rounded into smem A-frag layout (overlays dead buffers)
    float* sT2 = bufs;
    float2* sT2v2 = reinterpret_cast<float2*>(sT2);
    const int g = lane >> 2, tg = lane & 3;
    #pragma unroll
    for (int ni = 0; ni < 8; ni++) {
        const int nt = nw * 8 + ni;
        const int n2 = nt * 8 + 2 * tg;
        const int kk0 = n2 & 7, kk1 = kk0 + 1;
        const int base = (mw * 32 + nt) * 32;
        const int rgA = ((kk0 >> 2) & 1) << 1;
        const int i0 = (base + g * 4 + (kk0 & 3)) * 4 + rgA;
        const int i1 = (base + g * 4 + (kk1 & 3)) * 4 + rgA;
        const float b0 = fb2[n2], b1 = fb2[n2 + 1];
        sT2v2[i0 >> 1] = make_float2(f2tf_f(gelu_exact(c[ni][0] + b0)),
                                     f2tf_f(gelu_exact(c[ni][2] + b0)));
        sT2v2[i1 >> 1] = make_float2(f2tf_f(gelu_exact(c[ni][1] + b1)),
                                     f2tf_f(gelu_exact(c[ni][3] + b1)));
    }
    __syncthreads();

    // stage 3: [64,256] x [256,32]
    float c3[4] = {};
    #pragma unroll
    for (int ks = 0; ks < 32; ks++) {
        float4 a = reinterpret_cast<const float4*>(sT2)[(mw * 32 + ks) * 32 + lane];
        float2 bb = reinterpret_cast<const float2*>(sf3)[(nw * 32 + ks) * 32 + lane];
        mma_tf32(c3, a, bb);
    }

    const int col = nw * 8 + 2 * tg;
    const long rlo = r0 + mw * 16 + g, rhi = rlo + 8;
    const float b0 = fb3[col], b1 = fb3[col + 1];
    out[rlo * MD + col]     += c3[0] + b0;
    out[rlo * MD + col + 1] += c3[1] + b1;
    out[rhi * MD + col]     += c3[2] + b0;
    out[rhi * MD + col + 1] += c3[3] + b1;
}

extern "C" void kernel_launch(void* const* d_in, const int* in_sizes, int n_in,
                              void* d_out, int out_size) {
    const float* x   = (const float*)d_in[0];
    const float* psi = (const float*)d_in[1];
    const float* dw  = (const float*)d_in[2];
    const float* db  = (const float*)d_in[3];
    const float* hw1 = (const float*)d_in[4];
    const float* hb1 = (const float*)d_in[5];
    const float* hw2 = (const float*)d_in[6];
    const float* hb2 = (const float*)d_in[7];
    const float* fw1 = (const float*)d_in[8];
    const float* fb1 = (const float*)d_in[9];
    const float* fw2 = (const float*)d_in[10];
    const float* fb2 = (const float*)d_in[11];
    const float* fw3 = (const float*)d_in[12];
    const float* fb3 = (const float*)d_in[13];
    float* out = (float*)d_out;

    const size_t smD  = SMEM_D_F * sizeof(float);
    const size_t sm1  = (S1_AF + S1_BF) * sizeof(float);
    const size_t sm23 = S23_F * sizeof(float);
    cudaFuncSetAttribute(disco_head_mma, cudaFuncAttributeMaxDynamicSharedMemorySize, (int)smD);
    cudaFuncSetAttribute(ffn_s1, cudaFuncAttributeMaxDynamicSharedMemorySize, (int)sm1);
    cudaFuncSetAttribute(ffn_s2s3, cudaFuncAttributeMaxDynamicSharedMemorySize, (int)sm23);

    prep_weffB<<<H, 256>>>(dw, psi);
    prep_small<<<(HW1B_F + FW1B_F + FW3B_F + 255) / 256, 256>>>(hw1, fw1, fw3);
    prep_fw2B<<<FW2B_F / 256, 256>>>(fw2);
    disco_head_mma<<<dim3(W / TW, H, B), TA, smD>>>(x, db, hb1, hw2, hb2, out);
    ffn_s1<<<dim3((unsigned)(M_PIX / 64), 2), 512, sm1>>>(out, fb1);
    ffn_s2s3<<<(unsigned)(M_PIX / 64), 512, sm23>>>(fb2, fb3, out);
}